// round 11
// baseline (speedup 1.0000x reference)
#include <cuda_runtime.h>
#include <cuda_fp16.h>
#include <cstdint>
#include <math.h>

#define BB   4
#define SS   2048
#define HID  1024
#define NH   16
#define HD   64
#define ROWS (BB*SS)
#define QKVW (3*HID)
#define SCALE 0.125f   // 1/sqrt(64)

// Scratch (alloc-free rule: __device__ globals) — all fp16
__device__ __half g_xh[ROWS * HID];
__device__ __half g_QKVh[ROWS * QKVW];
__device__ __half g_AOh[ROWS * HID];
__device__ __half g_Wth[4 * HID * HID];

__device__ __forceinline__ void mma_f16(float* d, const uint32_t* a,
                                        const uint32_t* b) {
    asm volatile(
        "mma.sync.aligned.m16n8k16.row.col.f32.f16.f16.f32 "
        "{%0,%1,%2,%3}, {%4,%5,%6,%7}, {%8,%9}, {%0,%1,%2,%3};\n"
        : "+f"(d[0]), "+f"(d[1]), "+f"(d[2]), "+f"(d[3])
        : "r"(a[0]), "r"(a[1]), "r"(a[2]), "r"(a[3]), "r"(b[0]), "r"(b[1]));
}
__device__ __forceinline__ uint32_t h2u(__half2 h) { return *(uint32_t*)&h; }
__device__ __forceinline__ uint32_t sptr(const void* p) {
    uint32_t a;
    asm("{ .reg .u64 t; cvta.to.shared.u64 t, %1; cvt.u32.u64 %0, t; }"
        : "=r"(a) : "l"(p));
    return a;
}
#define LDSM_X4(r0, r1, r2, r3, addr)                                          \
    asm volatile("ldmatrix.sync.aligned.m8n8.x4.shared.b16 {%0,%1,%2,%3}, [%4];" \
                 : "=r"(r0), "=r"(r1), "=r"(r2), "=r"(r3) : "r"(addr))
#define LDSM_X4T(r0, r1, r2, r3, addr)                                         \
    asm volatile("ldmatrix.sync.aligned.m8n8.x4.trans.shared.b16 {%0,%1,%2,%3}, [%4];" \
                 : "=r"(r0), "=r"(r1), "=r"(r2), "=r"(r3) : "r"(addr))
#define CP16(dst, src)                                                         \
    asm volatile("cp.async.cg.shared.global [%0], [%1], 16;"                   \
                 :: "r"(dst), "l"(src))
#define CP_COMMIT() asm volatile("cp.async.commit_group;" ::: "memory")
#define CP_WAIT(n)  asm volatile("cp.async.wait_group %0;" :: "n"(n) : "memory")

// ---------------------------------------------------------------------------
// x -> half
// ---------------------------------------------------------------------------
__global__ __launch_bounds__(256) void cvt_x_kernel(const float* __restrict__ x)
{
    int idx = blockIdx.x * blockDim.x + threadIdx.x;
    float4 v = ((const float4*)x)[idx];
    uint2 u;
    u.x = h2u(__floats2half2_rn(v.x, v.y));
    u.y = h2u(__floats2half2_rn(v.z, v.w));
    ((uint2*)g_xh)[idx] = u;
}

// ---------------------------------------------------------------------------
// Weight transpose -> half
// ---------------------------------------------------------------------------
__global__ __launch_bounds__(256) void transpose_kernel(
    const float* __restrict__ W0, const float* __restrict__ W1,
    const float* __restrict__ W2, const float* __restrict__ W3)
{
    __shared__ float tile[32][33];
    const int z = blockIdx.z;
    const float* W = (z == 0) ? W0 : (z == 1) ? W1 : (z == 2) ? W2 : W3;
    __half* T = g_Wth + (size_t)z * HID * HID;
    const int k0 = blockIdx.x * 32, n0 = blockIdx.y * 32;
    const int tx = threadIdx.x & 31, ty = threadIdx.x >> 5;
#pragma unroll
    for (int r = 0; r < 4; r++)
        tile[ty + r * 8][tx] = W[(size_t)(k0 + ty + r * 8) * HID + n0 + tx];
    __syncthreads();
#pragma unroll
    for (int r = 0; r < 4; r++)
        T[(size_t)(n0 + ty + r * 8) * HID + k0 + tx] =
            __float2half(tile[tx][ty + r * 8]);
}

// ---------------------------------------------------------------------------
// fp16 GEMM: CTA tile 128x256, warp tile 64x64 (8 warps 2Mx4N), BK=32,
// 3-stage cp.async ring, ldmatrix fragments. Dynamic smem (92 KB).
// ---------------------------------------------------------------------------
#define GP 40
#define RG_SMEM (3 * (128 + 256) * GP * (int)sizeof(__half))   // 92160

template <typename OUT>
__global__ __launch_bounds__(256, 1) void rgemm_kernel(
    const __half* __restrict__ A, const __half* __restrict__ Bt,
    OUT* __restrict__ C, int ldc)
{
    extern __shared__ __half gsm[];
    __half* Asm = gsm;                       // [3][128][GP]
    __half* Bsm = gsm + 3 * 128 * GP;        // [3][256][GP]

    const int t    = threadIdx.x;
    const int wid  = t >> 5, lane = t & 31;
    const int gid  = lane >> 2, q4 = lane & 3;
    const int wm   = wid & 1;                // 0..1 -> 64-row strip
    const int wn   = wid >> 1;               // 0..3 -> 64-col strip
    const int bm   = blockIdx.y * 128;
    const int bn   = blockIdx.x * 256;
    const int lrow = t >> 1;                 // 0..127
    const int lch  = (t & 1) * 16;           // halves 0 or 16

    const __half* Ap  = A  + (size_t)(bm + lrow) * HID + lch;
    const __half* Bp0 = Bt + (size_t)(bn + lrow) * HID + lch;
    const __half* Bp1 = Bt + (size_t)(bn + lrow + 128) * HID + lch;

    uint32_t sa[3], sb0[3], sb1[3];
#pragma unroll
    for (int s = 0; s < 3; s++) {
        sa[s]  = sptr(&Asm[(s * 128 + lrow) * GP + lch]);
        sb0[s] = sptr(&Bsm[(s * 256 + lrow) * GP + lch]);
        sb1[s] = sptr(&Bsm[(s * 256 + lrow + 128) * GP + lch]);
    }

#define LD_STAGE(s, ko)                                   \
    do {                                                  \
        CP16(sa[s],       Ap  + (ko));                    \
        CP16(sa[s] + 16,  Ap  + (ko) + 8);                \
        CP16(sb0[s],      Bp0 + (ko));                    \
        CP16(sb0[s] + 16, Bp0 + (ko) + 8);                \
        CP16(sb1[s],      Bp1 + (ko));                    \
        CP16(sb1[s] + 16, Bp1 + (ko) + 8);                \
    } while (0)

    float acc[4][8][4];
#pragma unroll
    for (int mi = 0; mi < 4; mi++)
#pragma unroll
        for (int ni = 0; ni < 8; ni++)
#pragma unroll
            for (int e = 0; e < 4; e++) acc[mi][ni][e] = 0.f;

    LD_STAGE(0, 0);
    CP_COMMIT();
    LD_STAGE(1, 32);
    CP_COMMIT();
    CP_WAIT(1);
    __syncthreads();

    const int arow = lane & 15, acol8 = (lane >> 4) * 8;
    const int brow = ((lane >> 4) & 1) * 8 + (lane & 7), bcol8 = ((lane >> 3) & 1) * 8;

    const int NT = HID / 32;   // 32
    int cur = 0;
    for (int k = 0; k < NT; k++) {
        if (k + 2 < NT) {
            int ps = cur + 2; if (ps >= 3) ps -= 3;
            LD_STAGE(ps, (k + 2) * 32);
        }
        CP_COMMIT();

#pragma unroll
        for (int kf = 0; kf < 2; kf++) {
            uint32_t af[4][4], bf[8][2];
#pragma unroll
            for (int mi = 0; mi < 4; mi++) {
                uint32_t ad = sptr(&Asm[(cur * 128 + wm * 64 + mi * 16 + arow) * GP +
                                        kf * 16 + acol8]);
                LDSM_X4(af[mi][0], af[mi][1], af[mi][2], af[mi][3], ad);
            }
#pragma unroll
            for (int np = 0; np < 4; np++) {
                uint32_t bd = sptr(&Bsm[(cur * 256 + wn * 64 + np * 16 + brow) * GP +
                                        kf * 16 + bcol8]);
                LDSM_X4(bf[2 * np][0], bf[2 * np][1],
                        bf[2 * np + 1][0], bf[2 * np + 1][1], bd);
            }
#pragma unroll
            for (int mi = 0; mi < 4; mi++)
#pragma unroll
                for (int ni = 0; ni < 8; ni++)
                    mma_f16(acc[mi][ni], af[mi], bf[ni]);
        }

        CP_WAIT(1);
        __syncthreads();
        cur++; if (cur >= 3) cur = 0;
    }
#undef LD_STAGE

#pragma unroll
    for (int mi = 0; mi < 4; mi++) {
        const int r0 = bm + wm * 64 + mi * 16 + gid;
#pragma unroll
        for (int ni = 0; ni < 8; ni++) {
            const int col = bn + wn * 64 + ni * 8 + 2 * q4;
            if (sizeof(OUT) == 2) {
                *(uint32_t*)((__half*)C + (size_t)r0 * ldc + col) =
                    h2u(__floats2half2_rn(acc[mi][ni][0], acc[mi][ni][1]));
                *(uint32_t*)((__half*)C + (size_t)(r0 + 8) * ldc + col) =
                    h2u(__floats2half2_rn(acc[mi][ni][2], acc[mi][ni][3]));
            } else {
                *(float2*)((float*)C + (size_t)r0 * ldc + col) =
                    make_float2(acc[mi][ni][0], acc[mi][ni][1]);
                *(float2*)((float*)C + (size_t)(r0 + 8) * ldc + col) =
                    make_float2(acc[mi][ni][2], acc[mi][ni][3]);
            }
        }
    }
}

// ---------------------------------------------------------------------------
// RoPE in-place on half QKV (Q scaled by 1/sqrt(d)). fp32 math.
// ---------------------------------------------------------------------------
__global__ __launch_bounds__(256) void rope_kernel(__half* __restrict__ P)
{
    int idx = blockIdx.x * blockDim.x + threadIdx.x;
    int j2  = (idx & 15) * 2;
    int h   = (idx >> 4) & 31;
    int row = idx >> 9;
    int s   = row & (SS - 1);

    float c0, s0, c1, s1;
    {
        float inv0 = expf(-(float)j2 * (9.210340371976184f / 32.0f));
        float inv1 = expf(-(float)(j2 + 1) * (9.210340371976184f / 32.0f));
        sincosf((float)s * inv0, &s0, &c0);
        sincosf((float)s * inv1, &s1, &c1);
    }

    size_t base = (size_t)row * QKVW + h * HD + j2;
    __half2 hx1 = *(__half2*)&P[base];
    __half2 hx2 = *(__half2*)&P[base + 32];
    float x1a = __low2float(hx1), x1b = __high2float(hx1);
    float x2a = __low2float(hx2), x2b = __high2float(hx2);

    float y1a = x1a * c0 - x2a * s0, y1b = x1b * c1 - x2b * s1;
    float y2a = x2a * c0 + x1a * s0, y2b = x2b * c1 + x1b * s1;
    if (h < 16) { y1a *= SCALE; y1b *= SCALE; y2a *= SCALE; y2b *= SCALE; }

    *(__half2*)&P[base]      = __floats2half2_rn(y1a, y1b);
    *(__half2*)&P[base + 32] = __floats2half2_rn(y2a, y2b);
}

// ---------------------------------------------------------------------------
// Flash attention: fp16 mma + ldmatrix + cp.async KV double-buffer.
// P stays in registers (S C-frag == PV A-frag layout trick).
// ---------------------------------------------------------------------------
#define FP 72

__global__ __launch_bounds__(256, 2) void flashmma_kernel(
    const __half* __restrict__ QKV, __half* __restrict__ AO,
    const int* __restrict__ seq_lens)
{
    extern __shared__ __half smh[];
    __half* Ps = smh;                      // [128][FP] (Q staging)
    __half* Ks = Ps + 128 * FP;            // [2][64][FP]
    __half* Vs = Ks + 2 * 64 * FP;         // [2][64][FP]

    const int bx = blockIdx.x, h = blockIdx.y, b = blockIdx.z;
    const int sl = __ldg(&seq_lens[b]);
    const int q0 = bx * 128;
    const int t  = threadIdx.x;
    const int wid = t >> 5, lane = t & 31;
    const int gid = lane >> 2, q4 = lane & 3;
    const int wr  = wid * 16;

    const size_t qkv_base = (size_t)b * SS * QKVW + (size_t)h * HD;
    const size_t ao_base  = (size_t)b * SS * HID  + (size_t)h * HD;

    if (q0 >= sl) {
        for (int lin = t; lin < 128 * 8; lin += 256) {
            int r = lin >> 3, c8 = (lin & 7) * 8;
            *(uint4*)(AO + ao_base + (size_t)(q0 + r) * HID + c8) =
                make_uint4(0, 0, 0, 0);
        }
        return;
    }

    const int lr0 = t >> 2, lc0 = (t & 3) * 16;
#define LD_KV(stage, k0)                                                       \
    do {                                                                       \
        size_t off = qkv_base + (size_t)((k0) + lr0) * QKVW + lc0;             \
        uint32_t dk = sptr(&Ks[(stage) * 64 * FP + lr0 * FP + lc0]);           \
        uint32_t dv = sptr(&Vs[(stage) * 64 * FP + lr0 * FP + lc0]);           \
        CP16(dk,      QKV + off + HID);                                        \
        CP16(dk + 16, QKV + off + HID + 8);                                    \
        CP16(dv,      QKV + off + 2 * HID);                                    \
        CP16(dv + 16, QKV + off + 2 * HID + 8);                                \
    } while (0)

    const int n_kt = min(2 * bx + 2, (sl + 63) >> 6);

    LD_KV(0, 0);
    CP_COMMIT();
    for (int lin = t; lin < 128 * 8; lin += 256) {
        int r = lin >> 3, c8 = (lin & 7) * 8;
        CP16(sptr(&Ps[r * FP + c8]),
             QKV + qkv_base + (size_t)(q0 + r) * QKVW + c8);
    }
    CP_COMMIT();
    CP_WAIT(0);
    __syncthreads();

    const int arow = lane & 15, acol8 = (lane >> 4) * 8;
    uint32_t qa[4][4];
#pragma unroll
    for (int kf = 0; kf < 4; kf++) {
        uint32_t ad = sptr(&Ps[(wr + arow) * FP + kf * 16 + acol8]);
        LDSM_X4(qa[kf][0], qa[kf][1], qa[kf][2], qa[kf][3], ad);
    }

    float ofr[8][4];
#pragma unroll
    for (int nf = 0; nf < 8; nf++)
#pragma unroll
        for (int e = 0; e < 4; e++) ofr[nf][e] = 0.f;
    float m0 = -1e30f, m1 = -1e30f, l0 = 0.f, l1 = 0.f;

    const int r0g = q0 + wr + gid;
    const int r1g = r0g + 8;

    const int krow = lane & 7, kcol8 = (lane >> 3) * 8;
    const int vrow = lane & 15, vcol8 = ((lane >> 4) & 1) * 8;

    for (int kt = 0; kt < n_kt; kt++) {
        const int cur = kt & 1, nxt = cur ^ 1;
        const int k0 = kt * 64;

        __syncthreads();
        if (kt + 1 < n_kt) LD_KV(nxt, k0 + 64);
        CP_COMMIT();
        CP_WAIT(1);
        __syncthreads();

        const __half* Kc = Ks + cur * 64 * FP;
        const __half* Vc = Vs + cur * 64 * FP;

        // S = Q @ K^T
        float sfr[8][4];
#pragma unroll
        for (int nf = 0; nf < 8; nf++) {
#pragma unroll
            for (int e = 0; e < 4; e++) sfr[nf][e] = 0.f;
            uint32_t kb[4][2];
            uint32_t d0 = sptr(&Kc[(nf * 8 + krow) * FP + kcol8]);
            LDSM_X4(kb[0][0], kb[0][1], kb[1][0], kb[1][1], d0);
            uint32_t d1 = sptr(&Kc[(nf * 8 + krow) * FP + 32 + kcol8]);
            LDSM_X4(kb[2][0], kb[2][1], kb[3][0], kb[3][1], d1);
#pragma unroll
            for (int kf = 0; kf < 4; kf++)
                mma_f16(sfr[nf], qa[kf], kb[kf]);
        }

        if (k0 + 63 > q0 + wr) {
#pragma unroll
            for (int nf = 0; nf < 8; nf++) {
                int c0 = k0 + nf * 8 + 2 * q4, c1 = c0 + 1;
                if (c0 > r0g) sfr[nf][0] = -1e30f;
                if (c1 > r0g) sfr[nf][1] = -1e30f;
                if (c0 > r1g) sfr[nf][2] = -1e30f;
                if (c1 > r1g) sfr[nf][3] = -1e30f;
            }
        }

        float tm0 = -1e30f, tm1 = -1e30f;
#pragma unroll
        for (int nf = 0; nf < 8; nf++) {
            tm0 = fmaxf(tm0, fmaxf(sfr[nf][0], sfr[nf][1]));
            tm1 = fmaxf(tm1, fmaxf(sfr[nf][2], sfr[nf][3]));
        }
        tm0 = fmaxf(tm0, __shfl_xor_sync(0xffffffffu, tm0, 1));
        tm0 = fmaxf(tm0, __shfl_xor_sync(0xffffffffu, tm0, 2));
        tm1 = fmaxf(tm1, __shfl_xor_sync(0xffffffffu, tm1, 1));
        tm1 = fmaxf(tm1, __shfl_xor_sync(0xffffffffu, tm1, 2));

        float mn0 = fmaxf(m0, tm0), mn1 = fmaxf(m1, tm1);
        float corr0 = __expf(m0 - mn0), corr1 = __expf(m1 - mn1);
        m0 = mn0; m1 = mn1;

        float s0 = 0.f, s1 = 0.f;
#pragma unroll
        for (int nf = 0; nf < 8; nf++) {
            float p0 = __expf(sfr[nf][0] - mn0);
            float p1 = __expf(sfr[nf][1] - mn0);
            float p2 = __expf(sfr[nf][2] - mn1);
            float p3 = __expf(sfr[nf][3] - mn1);
            s0 += p0 + p1; s1 += p2 + p3;
            sfr[nf][0] = p0; sfr[nf][1] = p1;
            sfr[nf][2] = p2; sfr[nf][3] = p3;
        }
        s0 += __shfl_xor_sync(0xffffffffu, s0, 1);
        s0 += __shfl_xor_sync(0xffffffffu, s0, 2);
        s1 += __shfl_xor_sync(0xffffffffu, s1, 1);
        s1 += __shfl_xor_sync(0xffffffffu, s1, 2);
        l0 = l0 * corr0 + s0;
        l1 = l1 * corr1 + s1;

#pragma unroll
        for (int nf = 0; nf < 8; nf++) {
            ofr[nf][0] *= corr0; ofr[nf][1] *= corr0;
            ofr[nf][2] *= corr1; ofr[nf][3] *= corr1;
        }

        // P A-frags directly from S C-frags (no smem round-trip):
        // pa[kf] covers kv cols 16kf..16kf+15 = S tiles nf=2kf, 2kf+1.
        uint32_t pa[4][4];
#pragma unroll
        for (int kf = 0; kf < 4; kf++) {
            pa[kf][0] = h2u(__floats2half2_rn(sfr[2 * kf][0],     sfr[2 * kf][1]));
            pa[kf][1] = h2u(__floats2half2_rn(sfr[2 * kf][2],     sfr[2 * kf][3]));
            pa[kf][2] = h2u(__floats2half2_rn(sfr[2 * kf + 1][0], sfr[2 * kf + 1][1]));
            pa[kf][3] = h2u(__floats2half2_rn(sfr[2 * kf + 1][2], sfr[2 * kf + 1][3]));
        }

        // O += P @ V
#pragma unroll
        for (int np = 0; np < 4; np++) {
#pragma unroll
            for (int kf = 0; kf < 4; kf++) {
                uint32_t v0, v1, v2, v3;
                uint32_t vd = sptr(&Vc[(kf * 16 + vrow) * FP + np * 16 + vcol8]);
                LDSM_X4T(v0, v1, v2, v3, vd);
                uint32_t blo[2] = {v0, v1}, bhi[2] = {v2, v3};
                mma_f16(ofr[2 * np], pa[kf], blo);
                mma_f16(ofr[2 * np + 1], pa[kf], bhi);
            }
        }
    }
#undef LD_KV

    const float inv0 = (r0g < sl) ? (1.f / l0) : 0.f;
    const float inv1 = (r1g < sl) ? (1.f / l1) : 0.f;
#pragma unroll
    for (int nf = 0; nf < 8; nf++) {
        *(uint32_t*)(AO + ao_base + (size_t)r0g * HID + nf * 8 + 2 * q4) =
            h2u(__floats2half2_rn(ofr[nf][0] * inv0, ofr[nf][1] * inv0));
        *(uint32_t*)(AO + ao_base + (size_t)r1g * HID + nf * 8 + 2 * q4) =
            h2u(__floats2half2_rn(ofr[nf][2] * inv1, ofr[nf][3] * inv1));
    }
}

// ---------------------------------------------------------------------------
extern "C" void kernel_launch(void* const* d_in, const int* in_sizes, int n_in,
                              void* d_out, int out_size)
{
    (void)in_sizes; (void)n_in; (void)out_size;
    const float* x  = (const float*)d_in[0];
    const float* Wq = (const float*)d_in[1];
    const float* Wk = (const float*)d_in[2];
    const float* Wv = (const float*)d_in[3];
    const float* Wo = (const float*)d_in[4];
    const int*   sl = (const int*)d_in[5];
    float* out = (float*)d_out;

    __half *xh, *QKVh, *AOh, *Wth;
    cudaGetSymbolAddress((void**)&xh,   g_xh);
    cudaGetSymbolAddress((void**)&QKVh, g_QKVh);
    cudaGetSymbolAddress((void**)&AOh,  g_AOh);
    cudaGetSymbolAddress((void**)&Wth,  g_Wth);

    const int FLASH_SMEM = (128 + 4 * 64) * FP * (int)sizeof(__half); // 55296
    cudaFuncSetAttribute(flashmma_kernel,
                         cudaFuncAttributeMaxDynamicSharedMemorySize, FLASH_SMEM);
    cudaFuncSetAttribute(rgemm_kernel<__half>,
                         cudaFuncAttributeMaxDynamicSharedMemorySize, RG_SMEM);
    cudaFuncSetAttribute(rgemm_kernel<float>,
                         cudaFuncAttributeMaxDynamicSharedMemorySize, RG_SMEM);

    cvt_x_kernel<<<(ROWS * HID / 4) / 256, 256>>>(x);
    transpose_kernel<<<dim3(32, 32, 4), 256>>>(Wq, Wk, Wv, Wo);

    rgemm_kernel<__half><<<dim3(QKVW / 256, ROWS / 128), 256, RG_SMEM>>>(
        xh, Wth, QKVh, QKVW);

    rope_kernel<<<(ROWS * 32 * 16) / 256, 256>>>(QKVh);

    dim3 flash_grid(SS / 128, NH, BB);
    flashmma_kernel<<<flash_grid, 256, FLASH_SMEM>>>(QKVh, AOh, sl);

    rgemm_kernel<float><<<dim3(HID / 256, ROWS / 128), 256, RG_SMEM>>>(
        AOh, Wth + 3 * (size_t)HID * HID, out, HID);
}

// round 12
// speedup vs baseline: 1.0854x; 1.0854x over previous
#include <cuda_runtime.h>
#include <cuda_fp16.h>
#include <cstdint>
#include <math.h>

#define BB   4
#define SS   2048
#define HID  1024
#define NH   16
#define HD   64
#define ROWS (BB*SS)
#define QKVW (3*HID)
#define SCALE 0.125f   // 1/sqrt(64)

// Scratch (alloc-free rule: __device__ globals) — all fp16
__device__ __half g_xh[ROWS * HID];
__device__ __half g_QKVh[ROWS * QKVW];
__device__ __half g_AOh[ROWS * HID];
__device__ __half g_Wth[4 * HID * HID];

__device__ __forceinline__ void mma_f16(float* d, const uint32_t* a,
                                        const uint32_t* b) {
    asm volatile(
        "mma.sync.aligned.m16n8k16.row.col.f32.f16.f16.f32 "
        "{%0,%1,%2,%3}, {%4,%5,%6,%7}, {%8,%9}, {%0,%1,%2,%3};\n"
        : "+f"(d[0]), "+f"(d[1]), "+f"(d[2]), "+f"(d[3])
        : "r"(a[0]), "r"(a[1]), "r"(a[2]), "r"(a[3]), "r"(b[0]), "r"(b[1]));
}
__device__ __forceinline__ uint32_t h2u(__half2 h) { return *(uint32_t*)&h; }
__device__ __forceinline__ uint32_t sptr(const void* p) {
    uint32_t a;
    asm("{ .reg .u64 t; cvta.to.shared.u64 t, %1; cvt.u32.u64 %0, t; }"
        : "=r"(a) : "l"(p));
    return a;
}
#define LDSM_X4(r0, r1, r2, r3, addr)                                          \
    asm volatile("ldmatrix.sync.aligned.m8n8.x4.shared.b16 {%0,%1,%2,%3}, [%4];" \
                 : "=r"(r0), "=r"(r1), "=r"(r2), "=r"(r3) : "r"(addr))
#define LDSM_X4T(r0, r1, r2, r3, addr)                                         \
    asm volatile("ldmatrix.sync.aligned.m8n8.x4.trans.shared.b16 {%0,%1,%2,%3}, [%4];" \
                 : "=r"(r0), "=r"(r1), "=r"(r2), "=r"(r3) : "r"(addr))
#define CP16(dst, src)                                                         \
    asm volatile("cp.async.cg.shared.global [%0], [%1], 16;"                   \
                 :: "r"(dst), "l"(src))
#define CP_COMMIT() asm volatile("cp.async.commit_group;" ::: "memory")
#define CP_WAIT(n)  asm volatile("cp.async.wait_group %0;" :: "n"(n) : "memory")

// ---------------------------------------------------------------------------
// x -> half
// ---------------------------------------------------------------------------
__global__ __launch_bounds__(256) void cvt_x_kernel(const float* __restrict__ x)
{
    int idx = blockIdx.x * blockDim.x + threadIdx.x;
    float4 v = ((const float4*)x)[idx];
    uint2 u;
    u.x = h2u(__floats2half2_rn(v.x, v.y));
    u.y = h2u(__floats2half2_rn(v.z, v.w));
    ((uint2*)g_xh)[idx] = u;
}

// ---------------------------------------------------------------------------
// Weight transpose -> half
// ---------------------------------------------------------------------------
__global__ __launch_bounds__(256) void transpose_kernel(
    const float* __restrict__ W0, const float* __restrict__ W1,
    const float* __restrict__ W2, const float* __restrict__ W3)
{
    __shared__ float tile[32][33];
    const int z = blockIdx.z;
    const float* W = (z == 0) ? W0 : (z == 1) ? W1 : (z == 2) ? W2 : W3;
    __half* T = g_Wth + (size_t)z * HID * HID;
    const int k0 = blockIdx.x * 32, n0 = blockIdx.y * 32;
    const int tx = threadIdx.x & 31, ty = threadIdx.x >> 5;
#pragma unroll
    for (int r = 0; r < 4; r++)
        tile[ty + r * 8][tx] = W[(size_t)(k0 + ty + r * 8) * HID + n0 + tx];
    __syncthreads();
#pragma unroll
    for (int r = 0; r < 4; r++)
        T[(size_t)(n0 + ty + r * 8) * HID + k0 + tx] =
            __float2half(tile[tx][ty + r * 8]);
}

// ---------------------------------------------------------------------------
// fp16 GEMM, ldmatrix + 3-stage cp.async ring. Block 128x128, BK=32,
// 8 warps 2(M)x4(N), warp tile 64x32, 2 CTA/SM.  (Round-10 proven config.)
// ---------------------------------------------------------------------------
#define GP 40

template <typename OUT>
__global__ __launch_bounds__(256, 2) void rgemm_kernel(
    const __half* __restrict__ A, const __half* __restrict__ Bt,
    OUT* __restrict__ C, int ldc)
{
    __shared__ __half As[3][128][GP];
    __shared__ __half Bs[3][128][GP];

    const int t    = threadIdx.x;
    const int wid  = t >> 5, lane = t & 31;
    const int gid  = lane >> 2, q4 = lane & 3;
    const int wm   = wid & 1;
    const int wn   = wid >> 1;
    const int bm   = blockIdx.y * 128;
    const int bn   = blockIdx.x * 128;
    const int lrow = t >> 1;           // 0..127
    const int lch  = (t & 1) * 16;     // halves 0 or 16

    const __half* Ap = A  + (size_t)(bm + lrow) * HID + lch;
    const __half* Bp = Bt + (size_t)(bn + lrow) * HID + lch;

    uint32_t sa[3], sb[3];
#pragma unroll
    for (int s = 0; s < 3; s++) {
        sa[s] = sptr(&As[s][lrow][lch]);
        sb[s] = sptr(&Bs[s][lrow][lch]);
    }

#define LD_STAGE(s, ko)                                   \
    do {                                                  \
        CP16(sa[s],      Ap + (ko));                      \
        CP16(sa[s] + 16, Ap + (ko) + 8);                  \
        CP16(sb[s],      Bp + (ko));                      \
        CP16(sb[s] + 16, Bp + (ko) + 8);                  \
    } while (0)

    float acc[4][4][4];
#pragma unroll
    for (int mi = 0; mi < 4; mi++)
#pragma unroll
        for (int ni = 0; ni < 4; ni++)
#pragma unroll
            for (int e = 0; e < 4; e++) acc[mi][ni][e] = 0.f;

    LD_STAGE(0, 0);
    CP_COMMIT();
    LD_STAGE(1, 32);
    CP_COMMIT();
    CP_WAIT(1);
    __syncthreads();

    const int arow = (lane & 15), acol8 = (lane >> 4) * 8;
    const int brow = ((lane >> 4) & 1) * 8 + (lane & 7), bcol8 = ((lane >> 3) & 1) * 8;

    const int NT = HID / 32;   // 32
    int cur = 0;
    for (int k = 0; k < NT; k++) {
        if (k + 2 < NT) {
            int ps = cur + 2; if (ps >= 3) ps -= 3;
            LD_STAGE(ps, (k + 2) * 32);
        }
        CP_COMMIT();

#pragma unroll
        for (int kf = 0; kf < 2; kf++) {
            uint32_t af[4][4], bf[4][2];
#pragma unroll
            for (int mi = 0; mi < 4; mi++) {
                uint32_t ad = sptr(&As[cur][wm * 64 + mi * 16 + arow][kf * 16 + acol8]);
                LDSM_X4(af[mi][0], af[mi][1], af[mi][2], af[mi][3], ad);
            }
#pragma unroll
            for (int np = 0; np < 2; np++) {
                uint32_t bd = sptr(&Bs[cur][wn * 32 + np * 16 + brow][kf * 16 + bcol8]);
                LDSM_X4(bf[2 * np][0], bf[2 * np][1],
                        bf[2 * np + 1][0], bf[2 * np + 1][1], bd);
            }
#pragma unroll
            for (int mi = 0; mi < 4; mi++)
#pragma unroll
                for (int ni = 0; ni < 4; ni++)
                    mma_f16(acc[mi][ni], af[mi], bf[ni]);
        }

        CP_WAIT(1);
        __syncthreads();
        cur++; if (cur >= 3) cur = 0;
    }
#undef LD_STAGE

#pragma unroll
    for (int mi = 0; mi < 4; mi++) {
        const int r0 = bm + wm * 64 + mi * 16 + gid;
#pragma unroll
        for (int ni = 0; ni < 4; ni++) {
            const int col = bn + wn * 32 + ni * 8 + 2 * q4;
            if (sizeof(OUT) == 2) {
                *(uint32_t*)((__half*)C + (size_t)r0 * ldc + col) =
                    h2u(__floats2half2_rn(acc[mi][ni][0], acc[mi][ni][1]));
                *(uint32_t*)((__half*)C + (size_t)(r0 + 8) * ldc + col) =
                    h2u(__floats2half2_rn(acc[mi][ni][2], acc[mi][ni][3]));
            } else {
                *(float2*)((float*)C + (size_t)r0 * ldc + col) =
                    make_float2(acc[mi][ni][0], acc[mi][ni][1]);
                *(float2*)((float*)C + (size_t)(r0 + 8) * ldc + col) =
                    make_float2(acc[mi][ni][2], acc[mi][ni][3]);
            }
        }
    }
}

// ---------------------------------------------------------------------------
// RoPE in-place on half QKV (Q scaled by 1/sqrt(d)). fp32 math.
// ---------------------------------------------------------------------------
__global__ __launch_bounds__(256) void rope_kernel(__half* __restrict__ P)
{
    int idx = blockIdx.x * blockDim.x + threadIdx.x;
    int j2  = (idx & 15) * 2;
    int h   = (idx >> 4) & 31;
    int row = idx >> 9;
    int s   = row & (SS - 1);

    float c0, s0, c1, s1;
    {
        float inv0 = expf(-(float)j2 * (9.210340371976184f / 32.0f));
        float inv1 = expf(-(float)(j2 + 1) * (9.210340371976184f / 32.0f));
        sincosf((float)s * inv0, &s0, &c0);
        sincosf((float)s * inv1, &s1, &c1);
    }

    size_t base = (size_t)row * QKVW + h * HD + j2;
    __half2 hx1 = *(__half2*)&P[base];
    __half2 hx2 = *(__half2*)&P[base + 32];
    float x1a = __low2float(hx1), x1b = __high2float(hx1);
    float x2a = __low2float(hx2), x2b = __high2float(hx2);

    float y1a = x1a * c0 - x2a * s0, y1b = x1b * c1 - x2b * s1;
    float y2a = x2a * c0 + x1a * s0, y2b = x2b * c1 + x1b * s1;
    if (h < 16) { y1a *= SCALE; y1b *= SCALE; y2a *= SCALE; y2b *= SCALE; }

    *(__half2*)&P[base]      = __floats2half2_rn(y1a, y1b);
    *(__half2*)&P[base + 32] = __floats2half2_rn(y2a, y2b);
}

// ---------------------------------------------------------------------------
// Flash attention: fp16 mma + ldmatrix + cp.async KV double-buffer.
// P stays in registers (S C-frag == PV A-frag layout trick).  (Round-11 flash.)
// ---------------------------------------------------------------------------
#define FP 72

__global__ __launch_bounds__(256, 2) void flashmma_kernel(
    const __half* __restrict__ QKV, __half* __restrict__ AO,
    const int* __restrict__ seq_lens)
{
    extern __shared__ __half smh[];
    __half* Ps = smh;                      // [128][FP] (Q staging)
    __half* Ks = Ps + 128 * FP;            // [2][64][FP]
    __half* Vs = Ks + 2 * 64 * FP;         // [2][64][FP]

    const int bx = blockIdx.x, h = blockIdx.y, b = blockIdx.z;
    const int sl = __ldg(&seq_lens[b]);
    const int q0 = bx * 128;
    const int t  = threadIdx.x;
    const int wid = t >> 5, lane = t & 31;
    const int gid = lane >> 2, q4 = lane & 3;
    const int wr  = wid * 16;

    const size_t qkv_base = (size_t)b * SS * QKVW + (size_t)h * HD;
    const size_t ao_base  = (size_t)b * SS * HID  + (size_t)h * HD;

    if (q0 >= sl) {
        for (int lin = t; lin < 128 * 8; lin += 256) {
            int r = lin >> 3, c8 = (lin & 7) * 8;
            *(uint4*)(AO + ao_base + (size_t)(q0 + r) * HID + c8) =
                make_uint4(0, 0, 0, 0);
        }
        return;
    }

    const int lr0 = t >> 2, lc0 = (t & 3) * 16;
#define LD_KV(stage, k0)                                                       \
    do {                                                                       \
        size_t off = qkv_base + (size_t)((k0) + lr0) * QKVW + lc0;             \
        uint32_t dk = sptr(&Ks[(stage) * 64 * FP + lr0 * FP + lc0]);           \
        uint32_t dv = sptr(&Vs[(stage) * 64 * FP + lr0 * FP + lc0]);           \
        CP16(dk,      QKV + off + HID);                                        \
        CP16(dk + 16, QKV + off + HID + 8);                                    \
        CP16(dv,      QKV + off + 2 * HID);                                    \
        CP16(dv + 16, QKV + off + 2 * HID + 8);                                \
    } while (0)

    const int n_kt = min(2 * bx + 2, (sl + 63) >> 6);

    LD_KV(0, 0);
    CP_COMMIT();
    for (int lin = t; lin < 128 * 8; lin += 256) {
        int r = lin >> 3, c8 = (lin & 7) * 8;
        CP16(sptr(&Ps[r * FP + c8]),
             QKV + qkv_base + (size_t)(q0 + r) * QKVW + c8);
    }
    CP_COMMIT();
    CP_WAIT(0);
    __syncthreads();

    const int arow = lane & 15, acol8 = (lane >> 4) * 8;
    uint32_t qa[4][4];
#pragma unroll
    for (int kf = 0; kf < 4; kf++) {
        uint32_t ad = sptr(&Ps[(wr + arow) * FP + kf * 16 + acol8]);
        LDSM_X4(qa[kf][0], qa[kf][1], qa[kf][2], qa[kf][3], ad);
    }

    float ofr[8][4];
#pragma unroll
    for (int nf = 0; nf < 8; nf++)
#pragma unroll
        for (int e = 0; e < 4; e++) ofr[nf][e] = 0.f;
    float m0 = -1e30f, m1 = -1e30f, l0 = 0.f, l1 = 0.f;

    const int r0g = q0 + wr + gid;
    const int r1g = r0g + 8;

    const int krow = lane & 7, kcol8 = (lane >> 3) * 8;
    const int vrow = lane & 15, vcol8 = ((lane >> 4) & 1) * 8;

    for (int kt = 0; kt < n_kt; kt++) {
        const int cur = kt & 1, nxt = cur ^ 1;
        const int k0 = kt * 64;

        __syncthreads();
        if (kt + 1 < n_kt) LD_KV(nxt, k0 + 64);
        CP_COMMIT();
        CP_WAIT(1);
        __syncthreads();

        const __half* Kc = Ks + cur * 64 * FP;
        const __half* Vc = Vs + cur * 64 * FP;

        // S = Q @ K^T
        float sfr[8][4];
#pragma unroll
        for (int nf = 0; nf < 8; nf++) {
#pragma unroll
            for (int e = 0; e < 4; e++) sfr[nf][e] = 0.f;
            uint32_t kb[4][2];
            uint32_t d0 = sptr(&Kc[(nf * 8 + krow) * FP + kcol8]);
            LDSM_X4(kb[0][0], kb[0][1], kb[1][0], kb[1][1], d0);
            uint32_t d1 = sptr(&Kc[(nf * 8 + krow) * FP + 32 + kcol8]);
            LDSM_X4(kb[2][0], kb[2][1], kb[3][0], kb[3][1], d1);
#pragma unroll
            for (int kf = 0; kf < 4; kf++)
                mma_f16(sfr[nf], qa[kf], kb[kf]);
        }

        if (k0 + 63 > q0 + wr) {
#pragma unroll
            for (int nf = 0; nf < 8; nf++) {
                int c0 = k0 + nf * 8 + 2 * q4, c1 = c0 + 1;
                if (c0 > r0g) sfr[nf][0] = -1e30f;
                if (c1 > r0g) sfr[nf][1] = -1e30f;
                if (c0 > r1g) sfr[nf][2] = -1e30f;
                if (c1 > r1g) sfr[nf][3] = -1e30f;
            }
        }

        float tm0 = -1e30f, tm1 = -1e30f;
#pragma unroll
        for (int nf = 0; nf < 8; nf++) {
            tm0 = fmaxf(tm0, fmaxf(sfr[nf][0], sfr[nf][1]));
            tm1 = fmaxf(tm1, fmaxf(sfr[nf][2], sfr[nf][3]));
        }
        tm0 = fmaxf(tm0, __shfl_xor_sync(0xffffffffu, tm0, 1));
        tm0 = fmaxf(tm0, __shfl_xor_sync(0xffffffffu, tm0, 2));
        tm1 = fmaxf(tm1, __shfl_xor_sync(0xffffffffu, tm1, 1));
        tm1 = fmaxf(tm1, __shfl_xor_sync(0xffffffffu, tm1, 2));

        float mn0 = fmaxf(m0, tm0), mn1 = fmaxf(m1, tm1);
        float corr0 = __expf(m0 - mn0), corr1 = __expf(m1 - mn1);
        m0 = mn0; m1 = mn1;

        float s0 = 0.f, s1 = 0.f;
#pragma unroll
        for (int nf = 0; nf < 8; nf++) {
            float p0 = __expf(sfr[nf][0] - mn0);
            float p1 = __expf(sfr[nf][1] - mn0);
            float p2 = __expf(sfr[nf][2] - mn1);
            float p3 = __expf(sfr[nf][3] - mn1);
            s0 += p0 + p1; s1 += p2 + p3;
            sfr[nf][0] = p0; sfr[nf][1] = p1;
            sfr[nf][2] = p2; sfr[nf][3] = p3;
        }
        s0 += __shfl_xor_sync(0xffffffffu, s0, 1);
        s0 += __shfl_xor_sync(0xffffffffu, s0, 2);
        s1 += __shfl_xor_sync(0xffffffffu, s1, 1);
        s1 += __shfl_xor_sync(0xffffffffu, s1, 2);
        l0 = l0 * corr0 + s0;
        l1 = l1 * corr1 + s1;

#pragma unroll
        for (int nf = 0; nf < 8; nf++) {
            ofr[nf][0] *= corr0; ofr[nf][1] *= corr0;
            ofr[nf][2] *= corr1; ofr[nf][3] *= corr1;
        }

        // P A-frags directly from S C-frags (no smem round-trip)
        uint32_t pa[4][4];
#pragma unroll
        for (int kf = 0; kf < 4; kf++) {
            pa[kf][0] = h2u(__floats2half2_rn(sfr[2 * kf][0],     sfr[2 * kf][1]));
            pa[kf][1] = h2u(__floats2half2_rn(sfr[2 * kf][2],     sfr[2 * kf][3]));
            pa[kf][2] = h2u(__floats2half2_rn(sfr[2 * kf + 1][0], sfr[2 * kf + 1][1]));
            pa[kf][3] = h2u(__floats2half2_rn(sfr[2 * kf + 1][2], sfr[2 * kf + 1][3]));
        }

        // O += P @ V
#pragma unroll
        for (int np = 0; np < 4; np++) {
#pragma unroll
            for (int kf = 0; kf < 4; kf++) {
                uint32_t v0, v1, v2, v3;
                uint32_t vd = sptr(&Vc[(kf * 16 + vrow) * FP + np * 16 + vcol8]);
                LDSM_X4T(v0, v1, v2, v3, vd);
                uint32_t blo[2] = {v0, v1}, bhi[2] = {v2, v3};
                mma_f16(ofr[2 * np], pa[kf], blo);
                mma_f16(ofr[2 * np + 1], pa[kf], bhi);
            }
        }
    }
#undef LD_KV

    const float inv0 = (r0g < sl) ? (1.f / l0) : 0.f;
    const float inv1 = (r1g < sl) ? (1.f / l1) : 0.f;
#pragma unroll
    for (int nf = 0; nf < 8; nf++) {
        *(uint32_t*)(AO + ao_base + (size_t)r0g * HID + nf * 8 + 2 * q4) =
            h2u(__floats2half2_rn(ofr[nf][0] * inv0, ofr[nf][1] * inv0));
        *(uint32_t*)(AO + ao_base + (size_t)r1g * HID + nf * 8 + 2 * q4) =
            h2u(__floats2half2_rn(ofr[nf][2] * inv1, ofr[nf][3] * inv1));
    }
}

// ---------------------------------------------------------------------------
extern "C" void kernel_launch(void* const* d_in, const int* in_sizes, int n_in,
                              void* d_out, int out_size)
{
    (void)in_sizes; (void)n_in; (void)out_size;
    const float* x  = (const float*)d_in[0];
    const float* Wq = (const float*)d_in[1];
    const float* Wk = (const float*)d_in[2];
    const float* Wv = (const float*)d_in[3];
    const float* Wo = (const float*)d_in[4];
    const int*   sl = (const int*)d_in[5];
    float* out = (float*)d_out;

    __half *xh, *QKVh, *AOh, *Wth;
    cudaGetSymbolAddress((void**)&xh,   g_xh);
    cudaGetSymbolAddress((void**)&QKVh, g_QKVh);
    cudaGetSymbolAddress((void**)&AOh,  g_AOh);
    cudaGetSymbolAddress((void**)&Wth,  g_Wth);

    const int FLASH_SMEM = (128 + 4 * 64) * FP * (int)sizeof(__half); // 55296
    cudaFuncSetAttribute(flashmma_kernel,
                         cudaFuncAttributeMaxDynamicSharedMemorySize, FLASH_SMEM);

    cvt_x_kernel<<<(ROWS * HID / 4) / 256, 256>>>(x);
    transpose_kernel<<<dim3(32, 32, 4), 256>>>(Wq, Wk, Wv, Wo);

    rgemm_kernel<__half><<<dim3(QKVW / 128, ROWS / 128), 256>>>(
        xh, Wth, QKVh, QKVW);

    rope_kernel<<<(ROWS * 32 * 16) / 256, 256>>>(QKVh);

    dim3 flash_grid(SS / 128, NH, BB);
    flashmma_kernel<<<flash_grid, 256, FLASH_SMEM>>>(QKVh, AOh, sl);

    rgemm_kernel<float><<<dim3(HID / 128, ROWS / 128), 256>>>(
        AOh, Wth + 3 * (size_t)HID * HID, out, HID);
}

// round 13
// speedup vs baseline: 1.2929x; 1.1912x over previous
#include <cuda_runtime.h>
#include <cuda_fp16.h>
#include <cstdint>
#include <math.h>

#define BB   4
#define SS   2048
#define HID  1024
#define NH   16
#define HD   64
#define ROWS (BB*SS)
#define QKVW (3*HID)
#define SCALE 0.125f   // 1/sqrt(64)

// Scratch (alloc-free rule: __device__ globals) — all fp16
__device__ __half g_xh[ROWS * HID];
__device__ __half g_QKVh[ROWS * QKVW];
__device__ __half g_AOh[ROWS * HID];
__device__ __half g_Wth[4 * HID * HID];

__device__ __forceinline__ void mma_f16(float* d, const uint32_t* a,
                                        const uint32_t* b) {
    asm volatile(
        "mma.sync.aligned.m16n8k16.row.col.f32.f16.f16.f32 "
        "{%0,%1,%2,%3}, {%4,%5,%6,%7}, {%8,%9}, {%0,%1,%2,%3};\n"
        : "+f"(d[0]), "+f"(d[1]), "+f"(d[2]), "+f"(d[3])
        : "r"(a[0]), "r"(a[1]), "r"(a[2]), "r"(a[3]), "r"(b[0]), "r"(b[1]));
}
__device__ __forceinline__ uint32_t h2u(__half2 h) { return *(uint32_t*)&h; }
__device__ __forceinline__ uint32_t sptr(const void* p) {
    uint32_t a;
    asm("{ .reg .u64 t; cvta.to.shared.u64 t, %1; cvt.u32.u64 %0, t; }"
        : "=r"(a) : "l"(p));
    return a;
}
#define LDSM_X4(r0, r1, r2, r3, addr)                                          \
    asm volatile("ldmatrix.sync.aligned.m8n8.x4.shared.b16 {%0,%1,%2,%3}, [%4];" \
                 : "=r"(r0), "=r"(r1), "=r"(r2), "=r"(r3) : "r"(addr))
#define LDSM_X4T(r0, r1, r2, r3, addr)                                         \
    asm volatile("ldmatrix.sync.aligned.m8n8.x4.trans.shared.b16 {%0,%1,%2,%3}, [%4];" \
                 : "=r"(r0), "=r"(r1), "=r"(r2), "=r"(r3) : "r"(addr))
#define CP16(dst, src)                                                         \
    asm volatile("cp.async.cg.shared.global [%0], [%1], 16;"                   \
                 :: "r"(dst), "l"(src))
#define CP_COMMIT() asm volatile("cp.async.commit_group;" ::: "memory")
#define CP_WAIT(n)  asm volatile("cp.async.wait_group %0;" :: "n"(n) : "memory")

// ---------------------------------------------------------------------------
// x -> half
// ---------------------------------------------------------------------------
__global__ __launch_bounds__(256) void cvt_x_kernel(const float* __restrict__ x)
{
    int idx = blockIdx.x * blockDim.x + threadIdx.x;
    float4 v = ((const float4*)x)[idx];
    uint2 u;
    u.x = h2u(__floats2half2_rn(v.x, v.y));
    u.y = h2u(__floats2half2_rn(v.z, v.w));
    ((uint2*)g_xh)[idx] = u;
}

// ---------------------------------------------------------------------------
// Weight transpose -> half
// ---------------------------------------------------------------------------
__global__ __launch_bounds__(256) void transpose_kernel(
    const float* __restrict__ W0, const float* __restrict__ W1,
    const float* __restrict__ W2, const float* __restrict__ W3)
{
    __shared__ float tile[32][33];
    const int z = blockIdx.z;
    const float* W = (z == 0) ? W0 : (z == 1) ? W1 : (z == 2) ? W2 : W3;
    __half* T = g_Wth + (size_t)z * HID * HID;
    const int k0 = blockIdx.x * 32, n0 = blockIdx.y * 32;
    const int tx = threadIdx.x & 31, ty = threadIdx.x >> 5;
#pragma unroll
    for (int r = 0; r < 4; r++)
        tile[ty + r * 8][tx] = W[(size_t)(k0 + ty + r * 8) * HID + n0 + tx];
    __syncthreads();
#pragma unroll
    for (int r = 0; r < 4; r++)
        T[(size_t)(n0 + ty + r * 8) * HID + k0 + tx] =
            __float2half(tile[tx][ty + r * 8]);
}

// ---------------------------------------------------------------------------
// fp16 GEMM, ldmatrix + 3-stage cp.async ring. Block 128x128, BK=32,
// 8 warps 2(M)x4(N), warp tile 64x32, 2 CTA/SM.
// MODE 0 (QKV, half out): skip row-blocks entirely >= ceil64(seq_len) — those
//   QKV rows are provably never read by flash.
// MODE 1 (Wo, float out): row-blocks entirely >= seq_len write zeros (AO rows
//   there are exact zeros so the product is zero; d_out must be written).
// ---------------------------------------------------------------------------
#define GP 40

template <typename OUT, int MODE>
__global__ __launch_bounds__(256, 2) void rgemm_kernel(
    const __half* __restrict__ A, const __half* __restrict__ Bt,
    OUT* __restrict__ C, int ldc, const int* __restrict__ seq_lens)
{
    __shared__ __half As[3][128][GP];
    __shared__ __half Bs[3][128][GP];

    const int t    = threadIdx.x;
    const int bm   = blockIdx.y * 128;
    const int bn   = blockIdx.x * 128;

    const int slb = __ldg(&seq_lens[bm >> 11]);
    const int rloc = bm & (SS - 1);
    if (MODE == 0) {
        if (rloc >= ((slb + 63) & ~63)) return;   // never read downstream
    } else {
        if (rloc >= slb) {                        // output rows are zeros
            for (int lin = t; lin < 128 * 32; lin += 256) {
                int r = lin >> 5, c4 = (lin & 31) * 4;
                *(float4*)((float*)C + (size_t)(bm + r) * ldc + bn + c4) =
                    make_float4(0.f, 0.f, 0.f, 0.f);
            }
            return;
        }
    }

    const int wid  = t >> 5, lane = t & 31;
    const int gid  = lane >> 2, q4 = lane & 3;
    const int wm   = wid & 1;
    const int wn   = wid >> 1;
    const int lrow = t >> 1;           // 0..127
    const int lch  = (t & 1) * 16;     // halves 0 or 16

    const __half* Ap = A  + (size_t)(bm + lrow) * HID + lch;
    const __half* Bp = Bt + (size_t)(bn + lrow) * HID + lch;

    uint32_t sa[3], sb[3];
#pragma unroll
    for (int s = 0; s < 3; s++) {
        sa[s] = sptr(&As[s][lrow][lch]);
        sb[s] = sptr(&Bs[s][lrow][lch]);
    }

#define LD_STAGE(s, ko)                                   \
    do {                                                  \
        CP16(sa[s],      Ap + (ko));                      \
        CP16(sa[s] + 16, Ap + (ko) + 8);                  \
        CP16(sb[s],      Bp + (ko));                      \
        CP16(sb[s] + 16, Bp + (ko) + 8);                  \
    } while (0)

    float acc[4][4][4];
#pragma unroll
    for (int mi = 0; mi < 4; mi++)
#pragma unroll
        for (int ni = 0; ni < 4; ni++)
#pragma unroll
            for (int e = 0; e < 4; e++) acc[mi][ni][e] = 0.f;

    LD_STAGE(0, 0);
    CP_COMMIT();
    LD_STAGE(1, 32);
    CP_COMMIT();
    CP_WAIT(1);
    __syncthreads();

    const int arow = (lane & 15), acol8 = (lane >> 4) * 8;
    const int brow = ((lane >> 4) & 1) * 8 + (lane & 7), bcol8 = ((lane >> 3) & 1) * 8;

    const int NT = HID / 32;   // 32
    int cur = 0;
    for (int k = 0; k < NT; k++) {
        if (k + 2 < NT) {
            int ps = cur + 2; if (ps >= 3) ps -= 3;
            LD_STAGE(ps, (k + 2) * 32);
        }
        CP_COMMIT();

#pragma unroll
        for (int kf = 0; kf < 2; kf++) {
            uint32_t af[4][4], bf[4][2];
#pragma unroll
            for (int mi = 0; mi < 4; mi++) {
                uint32_t ad = sptr(&As[cur][wm * 64 + mi * 16 + arow][kf * 16 + acol8]);
                LDSM_X4(af[mi][0], af[mi][1], af[mi][2], af[mi][3], ad);
            }
#pragma unroll
            for (int np = 0; np < 2; np++) {
                uint32_t bd = sptr(&Bs[cur][wn * 32 + np * 16 + brow][kf * 16 + bcol8]);
                LDSM_X4(bf[2 * np][0], bf[2 * np][1],
                        bf[2 * np + 1][0], bf[2 * np + 1][1], bd);
            }
#pragma unroll
            for (int mi = 0; mi < 4; mi++)
#pragma unroll
                for (int ni = 0; ni < 4; ni++)
                    mma_f16(acc[mi][ni], af[mi], bf[ni]);
        }

        CP_WAIT(1);
        __syncthreads();
        cur++; if (cur >= 3) cur = 0;
    }
#undef LD_STAGE

#pragma unroll
    for (int mi = 0; mi < 4; mi++) {
        const int r0 = bm + wm * 64 + mi * 16 + gid;
#pragma unroll
        for (int ni = 0; ni < 4; ni++) {
            const int col = bn + wn * 32 + ni * 8 + 2 * q4;
            if (sizeof(OUT) == 2) {
                *(uint32_t*)((__half*)C + (size_t)r0 * ldc + col) =
                    h2u(__floats2half2_rn(acc[mi][ni][0], acc[mi][ni][1]));
                *(uint32_t*)((__half*)C + (size_t)(r0 + 8) * ldc + col) =
                    h2u(__floats2half2_rn(acc[mi][ni][2], acc[mi][ni][3]));
            } else {
                *(float2*)((float*)C + (size_t)r0 * ldc + col) =
                    make_float2(acc[mi][ni][0], acc[mi][ni][1]);
                *(float2*)((float*)C + (size_t)(r0 + 8) * ldc + col) =
                    make_float2(acc[mi][ni][2], acc[mi][ni][3]);
            }
        }
    }
}

// ---------------------------------------------------------------------------
// RoPE in-place on half QKV (Q scaled by 1/sqrt(d)). fp32 math.
// Skips rows past ceil64(seq_len) — never read downstream.
// ---------------------------------------------------------------------------
__global__ __launch_bounds__(256) void rope_kernel(
    __half* __restrict__ P, const int* __restrict__ seq_lens)
{
    int idx = blockIdx.x * blockDim.x + threadIdx.x;
    int j2  = (idx & 15) * 2;
    int h   = (idx >> 4) & 31;
    int row = idx >> 9;
    int s   = row & (SS - 1);

    const int slb = __ldg(&seq_lens[row >> 11]);
    if (s >= ((slb + 63) & ~63)) return;

    float c0, s0, c1, s1;
    {
        float inv0 = expf(-(float)j2 * (9.210340371976184f / 32.0f));
        float inv1 = expf(-(float)(j2 + 1) * (9.210340371976184f / 32.0f));
        sincosf((float)s * inv0, &s0, &c0);
        sincosf((float)s * inv1, &s1, &c1);
    }

    size_t base = (size_t)row * QKVW + h * HD + j2;
    __half2 hx1 = *(__half2*)&P[base];
    __half2 hx2 = *(__half2*)&P[base + 32];
    float x1a = __low2float(hx1), x1b = __high2float(hx1);
    float x2a = __low2float(hx2), x2b = __high2float(hx2);

    float y1a = x1a * c0 - x2a * s0, y1b = x1b * c1 - x2b * s1;
    float y2a = x2a * c0 + x1a * s0, y2b = x2b * c1 + x1b * s1;
    if (h < 16) { y1a *= SCALE; y1b *= SCALE; y2a *= SCALE; y2b *= SCALE; }

    *(__half2*)&P[base]      = __floats2half2_rn(y1a, y1b);
    *(__half2*)&P[base + 32] = __floats2half2_rn(y2a, y2b);
}

// ---------------------------------------------------------------------------
// Flash attention: fp16 mma + ldmatrix + cp.async KV double-buffer.
// P register-resident. Heavy blocks (large q0) launch first (bx reversed).
// ---------------------------------------------------------------------------
#define FP 72

__global__ __launch_bounds__(256, 2) void flashmma_kernel(
    const __half* __restrict__ QKV, __half* __restrict__ AO,
    const int* __restrict__ seq_lens)
{
    extern __shared__ __half smh[];
    __half* Ps = smh;                      // [128][FP] (Q staging)
    __half* Ks = Ps + 128 * FP;            // [2][64][FP]
    __half* Vs = Ks + 2 * 64 * FP;         // [2][64][FP]

    const int bx = (SS / 128 - 1) - blockIdx.x;   // heavy-first ordering
    const int h = blockIdx.y, b = blockIdx.z;
    const int sl = __ldg(&seq_lens[b]);
    const int q0 = bx * 128;
    const int t  = threadIdx.x;
    const int wid = t >> 5, lane = t & 31;
    const int gid = lane >> 2, q4 = lane & 3;
    const int wr  = wid * 16;

    const size_t qkv_base = (size_t)b * SS * QKVW + (size_t)h * HD;
    const size_t ao_base  = (size_t)b * SS * HID  + (size_t)h * HD;

    if (q0 >= sl) {
        for (int lin = t; lin < 128 * 8; lin += 256) {
            int r = lin >> 3, c8 = (lin & 7) * 8;
            *(uint4*)(AO + ao_base + (size_t)(q0 + r) * HID + c8) =
                make_uint4(0, 0, 0, 0);
        }
        return;
    }

    const int lr0 = t >> 2, lc0 = (t & 3) * 16;
#define LD_KV(stage, k0)                                                       \
    do {                                                                       \
        size_t off = qkv_base + (size_t)((k0) + lr0) * QKVW + lc0;             \
        uint32_t dk = sptr(&Ks[(stage) * 64 * FP + lr0 * FP + lc0]);           \
        uint32_t dv = sptr(&Vs[(stage) * 64 * FP + lr0 * FP + lc0]);           \
        CP16(dk,      QKV + off + HID);                                        \
        CP16(dk + 16, QKV + off + HID + 8);                                    \
        CP16(dv,      QKV + off + 2 * HID);                                    \
        CP16(dv + 16, QKV + off + 2 * HID + 8);                                \
    } while (0)

    const int n_kt = min(2 * bx + 2, (sl + 63) >> 6);

    LD_KV(0, 0);
    CP_COMMIT();
    for (int lin = t; lin < 128 * 8; lin += 256) {
        int r = lin >> 3, c8 = (lin & 7) * 8;
        CP16(sptr(&Ps[r * FP + c8]),
             QKV + qkv_base + (size_t)(q0 + r) * QKVW + c8);
    }
    CP_COMMIT();
    CP_WAIT(0);
    __syncthreads();

    const int arow = lane & 15, acol8 = (lane >> 4) * 8;
    uint32_t qa[4][4];
#pragma unroll
    for (int kf = 0; kf < 4; kf++) {
        uint32_t ad = sptr(&Ps[(wr + arow) * FP + kf * 16 + acol8]);
        LDSM_X4(qa[kf][0], qa[kf][1], qa[kf][2], qa[kf][3], ad);
    }

    float ofr[8][4];
#pragma unroll
    for (int nf = 0; nf < 8; nf++)
#pragma unroll
        for (int e = 0; e < 4; e++) ofr[nf][e] = 0.f;
    float m0 = -1e30f, m1 = -1e30f, l0 = 0.f, l1 = 0.f;

    const int r0g = q0 + wr + gid;
    const int r1g = r0g + 8;

    const int krow = lane & 7, kcol8 = (lane >> 3) * 8;
    const int vrow = lane & 15, vcol8 = ((lane >> 4) & 1) * 8;

    for (int kt = 0; kt < n_kt; kt++) {
        const int cur = kt & 1, nxt = cur ^ 1;
        const int k0 = kt * 64;

        __syncthreads();
        if (kt + 1 < n_kt) LD_KV(nxt, k0 + 64);
        CP_COMMIT();
        CP_WAIT(1);
        __syncthreads();

        const __half* Kc = Ks + cur * 64 * FP;
        const __half* Vc = Vs + cur * 64 * FP;

        // S = Q @ K^T
        float sfr[8][4];
#pragma unroll
        for (int nf = 0; nf < 8; nf++) {
#pragma unroll
            for (int e = 0; e < 4; e++) sfr[nf][e] = 0.f;
            uint32_t kb[4][2];
            uint32_t d0 = sptr(&Kc[(nf * 8 + krow) * FP + kcol8]);
            LDSM_X4(kb[0][0], kb[0][1], kb[1][0], kb[1][1], d0);
            uint32_t d1 = sptr(&Kc[(nf * 8 + krow) * FP + 32 + kcol8]);
            LDSM_X4(kb[2][0], kb[2][1], kb[3][0], kb[3][1], d1);
#pragma unroll
            for (int kf = 0; kf < 4; kf++)
                mma_f16(sfr[nf], qa[kf], kb[kf]);
        }

        if (k0 + 63 > q0 + wr) {
#pragma unroll
            for (int nf = 0; nf < 8; nf++) {
                int c0 = k0 + nf * 8 + 2 * q4, c1 = c0 + 1;
                if (c0 > r0g) sfr[nf][0] = -1e30f;
                if (c1 > r0g) sfr[nf][1] = -1e30f;
                if (c0 > r1g) sfr[nf][2] = -1e30f;
                if (c1 > r1g) sfr[nf][3] = -1e30f;
            }
        }

        float tm0 = -1e30f, tm1 = -1e30f;
#pragma unroll
        for (int nf = 0; nf < 8; nf++) {
            tm0 = fmaxf(tm0, fmaxf(sfr[nf][0], sfr[nf][1]));
            tm1 = fmaxf(tm1, fmaxf(sfr[nf][2], sfr[nf][3]));
        }
        tm0 = fmaxf(tm0, __shfl_xor_sync(0xffffffffu, tm0, 1));
        tm0 = fmaxf(tm0, __shfl_xor_sync(0xffffffffu, tm0, 2));
        tm1 = fmaxf(tm1, __shfl_xor_sync(0xffffffffu, tm1, 1));
        tm1 = fmaxf(tm1, __shfl_xor_sync(0xffffffffu, tm1, 2));

        float mn0 = fmaxf(m0, tm0), mn1 = fmaxf(m1, tm1);
        float corr0 = __expf(m0 - mn0), corr1 = __expf(m1 - mn1);
        m0 = mn0; m1 = mn1;

        float s0 = 0.f, s1 = 0.f;
#pragma unroll
        for (int nf = 0; nf < 8; nf++) {
            float p0 = __expf(sfr[nf][0] - mn0);
            float p1 = __expf(sfr[nf][1] - mn0);
            float p2 = __expf(sfr[nf][2] - mn1);
            float p3 = __expf(sfr[nf][3] - mn1);
            s0 += p0 + p1; s1 += p2 + p3;
            sfr[nf][0] = p0; sfr[nf][1] = p1;
            sfr[nf][2] = p2; sfr[nf][3] = p3;
        }
        s0 += __shfl_xor_sync(0xffffffffu, s0, 1);
        s0 += __shfl_xor_sync(0xffffffffu, s0, 2);
        s1 += __shfl_xor_sync(0xffffffffu, s1, 1);
        s1 += __shfl_xor_sync(0xffffffffu, s1, 2);
        l0 = l0 * corr0 + s0;
        l1 = l1 * corr1 + s1;

#pragma unroll
        for (int nf = 0; nf < 8; nf++) {
            ofr[nf][0] *= corr0; ofr[nf][1] *= corr0;
            ofr[nf][2] *= corr1; ofr[nf][3] *= corr1;
        }

        // P A-frags directly from S C-frags (no smem round-trip)
        uint32_t pa[4][4];
#pragma unroll
        for (int kf = 0; kf < 4; kf++) {
            pa[kf][0] = h2u(__floats2half2_rn(sfr[2 * kf][0],     sfr[2 * kf][1]));
            pa[kf][1] = h2u(__floats2half2_rn(sfr[2 * kf][2],     sfr[2 * kf][3]));
            pa[kf][2] = h2u(__floats2half2_rn(sfr[2 * kf + 1][0], sfr[2 * kf + 1][1]));
            pa[kf][3] = h2u(__floats2half2_rn(sfr[2 * kf + 1][2], sfr[2 * kf + 1][3]));
        }

        // O += P @ V
#pragma unroll
        for (int np = 0; np < 4; np++) {
#pragma unroll
            for (int kf = 0; kf < 4; kf++) {
                uint32_t v0, v1, v2, v3;
                uint32_t vd = sptr(&Vc[(kf * 16 + vrow) * FP + np * 16 + vcol8]);
                LDSM_X4T(v0, v1, v2, v3, vd);
                uint32_t blo[2] = {v0, v1}, bhi[2] = {v2, v3};
                mma_f16(ofr[2 * np], pa[kf], blo);
                mma_f16(ofr[2 * np + 1], pa[kf], bhi);
            }
        }
    }
#undef LD_KV

    const float inv0 = (r0g < sl) ? (1.f / l0) : 0.f;
    const float inv1 = (r1g < sl) ? (1.f / l1) : 0.f;
#pragma unroll
    for (int nf = 0; nf < 8; nf++) {
        *(uint32_t*)(AO + ao_base + (size_t)r0g * HID + nf * 8 + 2 * q4) =
            h2u(__floats2half2_rn(ofr[nf][0] * inv0, ofr[nf][1] * inv0));
        *(uint32_t*)(AO + ao_base + (size_t)r1g * HID + nf * 8 + 2 * q4) =
            h2u(__floats2half2_rn(ofr[nf][2] * inv1, ofr[nf][3] * inv1));
    }
}

// ---------------------------------------------------------------------------
extern "C" void kernel_launch(void* const* d_in, const int* in_sizes, int n_in,
                              void* d_out, int out_size)
{
    (void)in_sizes; (void)n_in; (void)out_size;
    const float* x  = (const float*)d_in[0];
    const float* Wq = (const float*)d_in[1];
    const float* Wk = (const float*)d_in[2];
    const float* Wv = (const float*)d_in[3];
    const float* Wo = (const float*)d_in[4];
    const int*   sl = (const int*)d_in[5];
    float* out = (float*)d_out;

    __half *xh, *QKVh, *AOh, *Wth;
    cudaGetSymbolAddress((void**)&xh,   g_xh);
    cudaGetSymbolAddress((void**)&QKVh, g_QKVh);
    cudaGetSymbolAddress((void**)&AOh,  g_AOh);
    cudaGetSymbolAddress((void**)&Wth,  g_Wth);

    const int FLASH_SMEM = (128 + 4 * 64) * FP * (int)sizeof(__half); // 55296
    cudaFuncSetAttribute(flashmma_kernel,
                         cudaFuncAttributeMaxDynamicSharedMemorySize, FLASH_SMEM);

    cvt_x_kernel<<<(ROWS * HID / 4) / 256, 256>>>(x);
    transpose_kernel<<<dim3(32, 32, 4), 256>>>(Wq, Wk, Wv, Wo);

    rgemm_kernel<__half, 0><<<dim3(QKVW / 128, ROWS / 128), 256>>>(
        xh, Wth, QKVh, QKVW, sl);

    rope_kernel<<<(ROWS * 32 * 16) / 256, 256>>>(QKVh, sl);

    dim3 flash_grid(SS / 128, NH, BB);
    flashmma_kernel<<<flash_grid, 256, FLASH_SMEM>>>(QKVh, AOh, sl);

    rgemm_kernel<float, 1><<<dim3(HID / 128, ROWS / 128), 256>>>(
        AOh, Wth + 3 * (size_t)HID * HID, out, HID, sl);
}

// round 14
// speedup vs baseline: 1.3021x; 1.0071x over previous
#include <cuda_runtime.h>
#include <cuda_fp16.h>
#include <cstdint>
#include <math.h>

#define BB   4
#define SS   2048
#define HID  1024
#define NH   16
#define HD   64
#define ROWS (BB*SS)
#define QKVW (3*HID)
#define SCALE 0.125f             // 1/sqrt(64)
#define QSCALE 0.18033688011112042f  // SCALE * log2(e)

// Scratch (alloc-free rule: __device__ globals) — all fp16
__device__ __half g_xh[ROWS * HID];
__device__ __half g_QKVh[ROWS * QKVW];
__device__ __half g_AOh[ROWS * HID];
__device__ __half g_Wth[4 * HID * HID];

__device__ __forceinline__ void mma_f16(float* d, const uint32_t* a,
                                        const uint32_t* b) {
    asm volatile(
        "mma.sync.aligned.m16n8k16.row.col.f32.f16.f16.f32 "
        "{%0,%1,%2,%3}, {%4,%5,%6,%7}, {%8,%9}, {%0,%1,%2,%3};\n"
        : "+f"(d[0]), "+f"(d[1]), "+f"(d[2]), "+f"(d[3])
        : "r"(a[0]), "r"(a[1]), "r"(a[2]), "r"(a[3]), "r"(b[0]), "r"(b[1]));
}
__device__ __forceinline__ uint32_t h2u(__half2 h) { return *(uint32_t*)&h; }
__device__ __forceinline__ float ex2f(float x) {
    float r;
    asm("ex2.approx.f32 %0, %1;" : "=f"(r) : "f"(x));
    return r;
}
__device__ __forceinline__ uint32_t sptr(const void* p) {
    uint32_t a;
    asm("{ .reg .u64 t; cvta.to.shared.u64 t, %1; cvt.u32.u64 %0, t; }"
        : "=r"(a) : "l"(p));
    return a;
}
#define LDSM_X4(r0, r1, r2, r3, addr)                                          \
    asm volatile("ldmatrix.sync.aligned.m8n8.x4.shared.b16 {%0,%1,%2,%3}, [%4];" \
                 : "=r"(r0), "=r"(r1), "=r"(r2), "=r"(r3) : "r"(addr))
#define LDSM_X4T(r0, r1, r2, r3, addr)                                         \
    asm volatile("ldmatrix.sync.aligned.m8n8.x4.trans.shared.b16 {%0,%1,%2,%3}, [%4];" \
                 : "=r"(r0), "=r"(r1), "=r"(r2), "=r"(r3) : "r"(addr))
#define CP16(dst, src)                                                         \
    asm volatile("cp.async.cg.shared.global [%0], [%1], 16;"                   \
                 :: "r"(dst), "l"(src))
#define CP_COMMIT() asm volatile("cp.async.commit_group;" ::: "memory")
#define CP_WAIT(n)  asm volatile("cp.async.wait_group %0;" :: "n"(n) : "memory")

// ---------------------------------------------------------------------------
// x -> half
// ---------------------------------------------------------------------------
__global__ __launch_bounds__(256) void cvt_x_kernel(const float* __restrict__ x)
{
    int idx = blockIdx.x * blockDim.x + threadIdx.x;
    float4 v = ((const float4*)x)[idx];
    uint2 u;
    u.x = h2u(__floats2half2_rn(v.x, v.y));
    u.y = h2u(__floats2half2_rn(v.z, v.w));
    ((uint2*)g_xh)[idx] = u;
}

// ---------------------------------------------------------------------------
// Weight transpose -> half
// ---------------------------------------------------------------------------
__global__ __launch_bounds__(256) void transpose_kernel(
    const float* __restrict__ W0, const float* __restrict__ W1,
    const float* __restrict__ W2, const float* __restrict__ W3)
{
    __shared__ float tile[32][33];
    const int z = blockIdx.z;
    const float* W = (z == 0) ? W0 : (z == 1) ? W1 : (z == 2) ? W2 : W3;
    __half* T = g_Wth + (size_t)z * HID * HID;
    const int k0 = blockIdx.x * 32, n0 = blockIdx.y * 32;
    const int tx = threadIdx.x & 31, ty = threadIdx.x >> 5;
#pragma unroll
    for (int r = 0; r < 4; r++)
        tile[ty + r * 8][tx] = W[(size_t)(k0 + ty + r * 8) * HID + n0 + tx];
    __syncthreads();
#pragma unroll
    for (int r = 0; r < 4; r++)
        T[(size_t)(n0 + ty + r * 8) * HID + k0 + tx] =
            __float2half(tile[tx][ty + r * 8]);
}

// ---------------------------------------------------------------------------
// fp16 GEMM, ldmatrix + 3-stage cp.async ring. Block 128x128, BK=32,
// 8 warps 2(M)x4(N), warp tile 64x32, 2 CTA/SM.  (Frozen from R13.)
// ---------------------------------------------------------------------------
#define GP 40

template <typename OUT, int MODE>
__global__ __launch_bounds__(256, 2) void rgemm_kernel(
    const __half* __restrict__ A, const __half* __restrict__ Bt,
    OUT* __restrict__ C, int ldc, const int* __restrict__ seq_lens)
{
    __shared__ __half As[3][128][GP];
    __shared__ __half Bs[3][128][GP];

    const int t    = threadIdx.x;
    const int bm   = blockIdx.y * 128;
    const int bn   = blockIdx.x * 128;

    const int slb = __ldg(&seq_lens[bm >> 11]);
    const int rloc = bm & (SS - 1);
    if (MODE == 0) {
        if (rloc >= ((slb + 63) & ~63)) return;
    } else {
        if (rloc >= slb) {
            for (int lin = t; lin < 128 * 32; lin += 256) {
                int r = lin >> 5, c4 = (lin & 31) * 4;
                *(float4*)((float*)C + (size_t)(bm + r) * ldc + bn + c4) =
                    make_float4(0.f, 0.f, 0.f, 0.f);
            }
            return;
        }
    }

    const int wid  = t >> 5, lane = t & 31;
    const int gid  = lane >> 2, q4 = lane & 3;
    const int wm   = wid & 1;
    const int wn   = wid >> 1;
    const int lrow = t >> 1;
    const int lch  = (t & 1) * 16;

    const __half* Ap = A  + (size_t)(bm + lrow) * HID + lch;
    const __half* Bp = Bt + (size_t)(bn + lrow) * HID + lch;

    uint32_t sa[3], sb[3];
#pragma unroll
    for (int s = 0; s < 3; s++) {
        sa[s] = sptr(&As[s][lrow][lch]);
        sb[s] = sptr(&Bs[s][lrow][lch]);
    }

#define LD_STAGE(s, ko)                                   \
    do {                                                  \
        CP16(sa[s],      Ap + (ko));                      \
        CP16(sa[s] + 16, Ap + (ko) + 8);                  \
        CP16(sb[s],      Bp + (ko));                      \
        CP16(sb[s] + 16, Bp + (ko) + 8);                  \
    } while (0)

    float acc[4][4][4];
#pragma unroll
    for (int mi = 0; mi < 4; mi++)
#pragma unroll
        for (int ni = 0; ni < 4; ni++)
#pragma unroll
            for (int e = 0; e < 4; e++) acc[mi][ni][e] = 0.f;

    LD_STAGE(0, 0);
    CP_COMMIT();
    LD_STAGE(1, 32);
    CP_COMMIT();
    CP_WAIT(1);
    __syncthreads();

    const int arow = (lane & 15), acol8 = (lane >> 4) * 8;
    const int brow = ((lane >> 4) & 1) * 8 + (lane & 7), bcol8 = ((lane >> 3) & 1) * 8;

    const int NT = HID / 32;
    int cur = 0;
    for (int k = 0; k < NT; k++) {
        if (k + 2 < NT) {
            int ps = cur + 2; if (ps >= 3) ps -= 3;
            LD_STAGE(ps, (k + 2) * 32);
        }
        CP_COMMIT();

#pragma unroll
        for (int kf = 0; kf < 2; kf++) {
            uint32_t af[4][4], bf[4][2];
#pragma unroll
            for (int mi = 0; mi < 4; mi++) {
                uint32_t ad = sptr(&As[cur][wm * 64 + mi * 16 + arow][kf * 16 + acol8]);
                LDSM_X4(af[mi][0], af[mi][1], af[mi][2], af[mi][3], ad);
            }
#pragma unroll
            for (int np = 0; np < 2; np++) {
                uint32_t bd = sptr(&Bs[cur][wn * 32 + np * 16 + brow][kf * 16 + bcol8]);
                LDSM_X4(bf[2 * np][0], bf[2 * np][1],
                        bf[2 * np + 1][0], bf[2 * np + 1][1], bd);
            }
#pragma unroll
            for (int mi = 0; mi < 4; mi++)
#pragma unroll
                for (int ni = 0; ni < 4; ni++)
                    mma_f16(acc[mi][ni], af[mi], bf[ni]);
        }

        CP_WAIT(1);
        __syncthreads();
        cur++; if (cur >= 3) cur = 0;
    }
#undef LD_STAGE

#pragma unroll
    for (int mi = 0; mi < 4; mi++) {
        const int r0 = bm + wm * 64 + mi * 16 + gid;
#pragma unroll
        for (int ni = 0; ni < 4; ni++) {
            const int col = bn + wn * 32 + ni * 8 + 2 * q4;
            if (sizeof(OUT) == 2) {
                *(uint32_t*)((__half*)C + (size_t)r0 * ldc + col) =
                    h2u(__floats2half2_rn(acc[mi][ni][0], acc[mi][ni][1]));
                *(uint32_t*)((__half*)C + (size_t)(r0 + 8) * ldc + col) =
                    h2u(__floats2half2_rn(acc[mi][ni][2], acc[mi][ni][3]));
            } else {
                *(float2*)((float*)C + (size_t)r0 * ldc + col) =
                    make_float2(acc[mi][ni][0], acc[mi][ni][1]);
                *(float2*)((float*)C + (size_t)(r0 + 8) * ldc + col) =
                    make_float2(acc[mi][ni][2], acc[mi][ni][3]);
            }
        }
    }
}

// ---------------------------------------------------------------------------
// RoPE in-place on half QKV. Q scaled by SCALE*log2(e) (flash uses ex2).
// Skips rows past ceil64(seq_len).
// ---------------------------------------------------------------------------
__global__ __launch_bounds__(256) void rope_kernel(
    __half* __restrict__ P, const int* __restrict__ seq_lens)
{
    int idx = blockIdx.x * blockDim.x + threadIdx.x;
    int j2  = (idx & 15) * 2;
    int h   = (idx >> 4) & 31;
    int row = idx >> 9;
    int s   = row & (SS - 1);

    const int slb = __ldg(&seq_lens[row >> 11]);
    if (s >= ((slb + 63) & ~63)) return;

    float c0, s0, c1, s1;
    {
        float inv0 = expf(-(float)j2 * (9.210340371976184f / 32.0f));
        float inv1 = expf(-(float)(j2 + 1) * (9.210340371976184f / 32.0f));
        sincosf((float)s * inv0, &s0, &c0);
        sincosf((float)s * inv1, &s1, &c1);
    }

    size_t base = (size_t)row * QKVW + h * HD + j2;
    __half2 hx1 = *(__half2*)&P[base];
    __half2 hx2 = *(__half2*)&P[base + 32];
    float x1a = __low2float(hx1), x1b = __high2float(hx1);
    float x2a = __low2float(hx2), x2b = __high2float(hx2);

    float y1a = x1a * c0 - x2a * s0, y1b = x1b * c1 - x2b * s1;
    float y2a = x2a * c0 + x1a * s0, y2b = x2b * c1 + x1b * s1;
    if (h < 16) { y1a *= QSCALE; y1b *= QSCALE; y2a *= QSCALE; y2b *= QSCALE; }

    *(__half2*)&P[base]      = __floats2half2_rn(y1a, y1b);
    *(__half2*)&P[base + 32] = __floats2half2_rn(y2a, y2b);
}

// ---------------------------------------------------------------------------
// Flash attention: fp16 mma + ldmatrix + 3-stage cp.async KV ring with a
// SINGLE barrier per kv-tile. P register-resident. Softmax in log2 domain
// (Q pre-scaled by log2e; ex2.approx for exponentials).
// ---------------------------------------------------------------------------
#define FP 72

__global__ __launch_bounds__(256, 2) void flashmma_kernel(
    const __half* __restrict__ QKV, __half* __restrict__ AO,
    const int* __restrict__ seq_lens)
{
    extern __shared__ __half smh[];
    __half* Ps = smh;                      // [128][FP] (Q staging)
    __half* Ks = Ps + 128 * FP;            // [3][64][FP]
    __half* Vs = Ks + 3 * 64 * FP;         // [3][64][FP]

    const int bx = (SS / 128 - 1) - blockIdx.x;   // heavy-first ordering
    const int h = blockIdx.y, b = blockIdx.z;
    const int sl = __ldg(&seq_lens[b]);
    const int q0 = bx * 128;
    const int t  = threadIdx.x;
    const int wid = t >> 5, lane = t & 31;
    const int gid = lane >> 2, q4 = lane & 3;
    const int wr  = wid * 16;

    const size_t qkv_base = (size_t)b * SS * QKVW + (size_t)h * HD;
    const size_t ao_base  = (size_t)b * SS * HID  + (size_t)h * HD;

    if (q0 >= sl) {
        for (int lin = t; lin < 128 * 8; lin += 256) {
            int r = lin >> 3, c8 = (lin & 7) * 8;
            *(uint4*)(AO + ao_base + (size_t)(q0 + r) * HID + c8) =
                make_uint4(0, 0, 0, 0);
        }
        return;
    }

    const int lr0 = t >> 2, lc0 = (t & 3) * 16;
#define LD_KV(stage, k0)                                                       \
    do {                                                                       \
        size_t off = qkv_base + (size_t)((k0) + lr0) * QKVW + lc0;             \
        uint32_t dk = sptr(&Ks[(stage) * 64 * FP + lr0 * FP + lc0]);           \
        uint32_t dv = sptr(&Vs[(stage) * 64 * FP + lr0 * FP + lc0]);           \
        CP16(dk,      QKV + off + HID);                                        \
        CP16(dk + 16, QKV + off + HID + 8);                                    \
        CP16(dv,      QKV + off + 2 * HID);                                    \
        CP16(dv + 16, QKV + off + 2 * HID + 8);                                \
    } while (0)

    const int n_kt = min(2 * bx + 2, (sl + 63) >> 6);

    // Prologue: stages 0 and 1 + Q staging, wait all.
    LD_KV(0, 0);
    if (n_kt > 1) LD_KV(1, 64);
    for (int lin = t; lin < 128 * 8; lin += 256) {
        int r = lin >> 3, c8 = (lin & 7) * 8;
        CP16(sptr(&Ps[r * FP + c8]),
             QKV + qkv_base + (size_t)(q0 + r) * QKVW + c8);
    }
    CP_COMMIT();
    CP_WAIT(0);
    __syncthreads();

    const int arow = lane & 15, acol8 = (lane >> 4) * 8;
    uint32_t qa[4][4];
#pragma unroll
    for (int kf = 0; kf < 4; kf++) {
        uint32_t ad = sptr(&Ps[(wr + arow) * FP + kf * 16 + acol8]);
        LDSM_X4(qa[kf][0], qa[kf][1], qa[kf][2], qa[kf][3], ad);
    }

    float ofr[8][4];
#pragma unroll
    for (int nf = 0; nf < 8; nf++)
#pragma unroll
        for (int e = 0; e < 4; e++) ofr[nf][e] = 0.f;
    float m0 = -1e30f, m1 = -1e30f, l0 = 0.f, l1 = 0.f;

    const int r0g = q0 + wr + gid;
    const int r1g = r0g + 8;

    const int krow = lane & 7, kcol8 = (lane >> 3) * 8;
    const int vrow = lane & 15, vcol8 = ((lane >> 4) & 1) * 8;

    int cur = 0;
    for (int kt = 0; kt < n_kt; kt++) {
        const int k0 = kt * 64;

        // Single barrier: frees stage (kt-1)%3 (the LD target below) and
        // publishes stage kt (each thread retired its group last iter).
        __syncthreads();
        if (kt + 2 < n_kt) {
            int ps = cur + 2; if (ps >= 3) ps -= 3;
            LD_KV(ps, k0 + 128);
        }
        CP_COMMIT();
        CP_WAIT(1);          // retires group for stage kt+1 (next iter's data)

        const __half* Kc = Ks + cur * 64 * FP;
        const __half* Vc = Vs + cur * 64 * FP;

        // S = Q @ K^T (log2 domain)
        float sfr[8][4];
#pragma unroll
        for (int nf = 0; nf < 8; nf++) {
#pragma unroll
            for (int e = 0; e < 4; e++) sfr[nf][e] = 0.f;
            uint32_t kb[4][2];
            uint32_t d0 = sptr(&Kc[(nf * 8 + krow) * FP + kcol8]);
            LDSM_X4(kb[0][0], kb[0][1], kb[1][0], kb[1][1], d0);
            uint32_t d1 = sptr(&Kc[(nf * 8 + krow) * FP + 32 + kcol8]);
            LDSM_X4(kb[2][0], kb[2][1], kb[3][0], kb[3][1], d1);
#pragma unroll
            for (int kf = 0; kf < 4; kf++)
                mma_f16(sfr[nf], qa[kf], kb[kf]);
        }

        if (k0 + 63 > q0 + wr) {
#pragma unroll
            for (int nf = 0; nf < 8; nf++) {
                int c0 = k0 + nf * 8 + 2 * q4, c1 = c0 + 1;
                if (c0 > r0g) sfr[nf][0] = -1e30f;
                if (c1 > r0g) sfr[nf][1] = -1e30f;
                if (c0 > r1g) sfr[nf][2] = -1e30f;
                if (c1 > r1g) sfr[nf][3] = -1e30f;
            }
        }

        float tm0 = -1e30f, tm1 = -1e30f;
#pragma unroll
        for (int nf = 0; nf < 8; nf++) {
            tm0 = fmaxf(tm0, fmaxf(sfr[nf][0], sfr[nf][1]));
            tm1 = fmaxf(tm1, fmaxf(sfr[nf][2], sfr[nf][3]));
        }
        tm0 = fmaxf(tm0, __shfl_xor_sync(0xffffffffu, tm0, 1));
        tm0 = fmaxf(tm0, __shfl_xor_sync(0xffffffffu, tm0, 2));
        tm1 = fmaxf(tm1, __shfl_xor_sync(0xffffffffu, tm1, 1));
        tm1 = fmaxf(tm1, __shfl_xor_sync(0xffffffffu, tm1, 2));

        float mn0 = fmaxf(m0, tm0), mn1 = fmaxf(m1, tm1);
        float corr0 = ex2f(m0 - mn0), corr1 = ex2f(m1 - mn1);
        m0 = mn0; m1 = mn1;

        float s0 = 0.f, s1 = 0.f;
#pragma unroll
        for (int nf = 0; nf < 8; nf++) {
            float p0 = ex2f(sfr[nf][0] - mn0);
            float p1 = ex2f(sfr[nf][1] - mn0);
            float p2 = ex2f(sfr[nf][2] - mn1);
            float p3 = ex2f(sfr[nf][3] - mn1);
            s0 += p0 + p1; s1 += p2 + p3;
            sfr[nf][0] = p0; sfr[nf][1] = p1;
            sfr[nf][2] = p2; sfr[nf][3] = p3;
        }
        s0 += __shfl_xor_sync(0xffffffffu, s0, 1);
        s0 += __shfl_xor_sync(0xffffffffu, s0, 2);
        s1 += __shfl_xor_sync(0xffffffffu, s1, 1);
        s1 += __shfl_xor_sync(0xffffffffu, s1, 2);
        l0 = l0 * corr0 + s0;
        l1 = l1 * corr1 + s1;

#pragma unroll
        for (int nf = 0; nf < 8; nf++) {
            ofr[nf][0] *= corr0; ofr[nf][1] *= corr0;
            ofr[nf][2] *= corr1; ofr[nf][3] *= corr1;
        }

        // P A-frags directly from S C-frags (register-resident P)
        uint32_t pa[4][4];
#pragma unroll
        for (int kf = 0; kf < 4; kf++) {
            pa[kf][0] = h2u(__floats2half2_rn(sfr[2 * kf][0],     sfr[2 * kf][1]));
            pa[kf][1] = h2u(__floats2half2_rn(sfr[2 * kf][2],     sfr[2 * kf][3]));
            pa[kf][2] = h2u(__floats2half2_rn(sfr[2 * kf + 1][0], sfr[2 * kf + 1][1]));
            pa[kf][3] = h2u(__floats2half2_rn(sfr[2 * kf + 1][2], sfr[2 * kf + 1][3]));
        }

        // O += P @ V
#pragma unroll
        for (int np = 0; np < 4; np++) {
#pragma unroll
            for (int kf = 0; kf < 4; kf++) {
                uint32_t v0, v1, v2, v3;
                uint32_t vd = sptr(&Vc[(kf * 16 + vrow) * FP + np * 16 + vcol8]);
                LDSM_X4T(v0, v1, v2, v3, vd);
                uint32_t blo[2] = {v0, v1}, bhi[2] = {v2, v3};
                mma_f16(ofr[2 * np], pa[kf], blo);
                mma_f16(ofr[2 * np + 1], pa[kf], bhi);
            }
        }

        cur++; if (cur >= 3) cur = 0;
    }
#undef LD_KV

    const float inv0 = (r0g < sl) ? (1.f / l0) : 0.f;
    const float inv1 = (r1g < sl) ? (1.f / l1) : 0.f;
#pragma unroll
    for (int nf = 0; nf < 8; nf++) {
        *(uint32_t*)(AO + ao_base + (size_t)r0g * HID + nf * 8 + 2 * q4) =
            h2u(__floats2half2_rn(ofr[nf][0] * inv0, ofr[nf][1] * inv0));
        *(uint32_t*)(AO + ao_base + (size_t)r1g * HID + nf * 8 + 2 * q4) =
            h2u(__floats2half2_rn(ofr[nf][2] * inv1, ofr[nf][3] * inv1));
    }
}

// ---------------------------------------------------------------------------
extern "C" void kernel_launch(void* const* d_in, const int* in_sizes, int n_in,
                              void* d_out, int out_size)
{
    (void)in_sizes; (void)n_in; (void)out_size;
    const float* x  = (const float*)d_in[0];
    const float* Wq = (const float*)d_in[1];
    const float* Wk = (const float*)d_in[2];
    const float* Wv = (const float*)d_in[3];
    const float* Wo = (const float*)d_in[4];
    const int*   sl = (const int*)d_in[5];
    float* out = (float*)d_out;

    __half *xh, *QKVh, *AOh, *Wth;
    cudaGetSymbolAddress((void**)&xh,   g_xh);
    cudaGetSymbolAddress((void**)&QKVh, g_QKVh);
    cudaGetSymbolAddress((void**)&AOh,  g_AOh);
    cudaGetSymbolAddress((void**)&Wth,  g_Wth);

    const int FLASH_SMEM = (128 + 6 * 64) * FP * (int)sizeof(__half); // 73728
    cudaFuncSetAttribute(flashmma_kernel,
                         cudaFuncAttributeMaxDynamicSharedMemorySize, FLASH_SMEM);

    cvt_x_kernel<<<(ROWS * HID / 4) / 256, 256>>>(x);
    transpose_kernel<<<dim3(32, 32, 4), 256>>>(Wq, Wk, Wv, Wo);

    rgemm_kernel<__half, 0><<<dim3(QKVW / 128, ROWS / 128), 256>>>(
        xh, Wth, QKVh, QKVW, sl);

    rope_kernel<<<(ROWS * 32 * 16) / 256, 256>>>(QKVh, sl);

    dim3 flash_grid(SS / 128, NH, BB);
    flashmma_kernel<<<flash_grid, 256, FLASH_SMEM>>>(QKVh, AOh, sl);

    rgemm_kernel<float, 1><<<dim3(HID / 128, ROWS / 128), 256>>>(
        AOh, Wth + 3 * (size_t)HID * HID, out, HID, sl);
}

// round 15
// speedup vs baseline: 1.3651x; 1.0484x over previous
#include <cuda_runtime.h>
#include <cuda_fp16.h>
#include <cstdint>
#include <math.h>

#define BB   4
#define SS   2048
#define HID  1024
#define NH   16
#define HD   64
#define ROWS (BB*SS)
#define QKVW (3*HID)
#define QSCALE 0.18033688011112042f  // (1/sqrt(64)) * log2(e)

// Scratch (alloc-free rule: __device__ globals)
__device__ __half g_xh[ROWS * HID];
__device__ __half g_QKVh[ROWS * QKVW];
__device__ __half g_AOh[ROWS * HID];
__device__ __half g_Wth[4 * HID * HID];
__device__ float2 g_rope[SS * 32];        // [s][j] = (cos, sin)

__device__ __forceinline__ void mma_f16(float* d, const uint32_t* a,
                                        const uint32_t* b) {
    asm volatile(
        "mma.sync.aligned.m16n8k16.row.col.f32.f16.f16.f32 "
        "{%0,%1,%2,%3}, {%4,%5,%6,%7}, {%8,%9}, {%0,%1,%2,%3};\n"
        : "+f"(d[0]), "+f"(d[1]), "+f"(d[2]), "+f"(d[3])
        : "r"(a[0]), "r"(a[1]), "r"(a[2]), "r"(a[3]), "r"(b[0]), "r"(b[1]));
}
__device__ __forceinline__ uint32_t h2u(__half2 h) { return *(uint32_t*)&h; }
__device__ __forceinline__ float ex2f(float x) {
    float r;
    asm("ex2.approx.f32 %0, %1;" : "=f"(r) : "f"(x));
    return r;
}
__device__ __forceinline__ uint32_t sptr(const void* p) {
    uint32_t a;
    asm("{ .reg .u64 t; cvta.to.shared.u64 t, %1; cvt.u32.u64 %0, t; }"
        : "=r"(a) : "l"(p));
    return a;
}
#define LDSM_X4(r0, r1, r2, r3, addr)                                          \
    asm volatile("ldmatrix.sync.aligned.m8n8.x4.shared.b16 {%0,%1,%2,%3}, [%4];" \
                 : "=r"(r0), "=r"(r1), "=r"(r2), "=r"(r3) : "r"(addr))
#define LDSM_X4T(r0, r1, r2, r3, addr)                                         \
    asm volatile("ldmatrix.sync.aligned.m8n8.x4.trans.shared.b16 {%0,%1,%2,%3}, [%4];" \
                 : "=r"(r0), "=r"(r1), "=r"(r2), "=r"(r3) : "r"(addr))
#define CP16(dst, src)                                                         \
    asm volatile("cp.async.cg.shared.global [%0], [%1], 16;"                   \
                 :: "r"(dst), "l"(src))
#define CP_COMMIT() asm volatile("cp.async.commit_group;" ::: "memory")
#define CP_WAIT(n)  asm volatile("cp.async.wait_group %0;" :: "n"(n) : "memory")

// ---------------------------------------------------------------------------
// RoPE cos/sin table: g_rope[s][j], j = rotation-pair index 0..31.
// ---------------------------------------------------------------------------
__global__ __launch_bounds__(256) void rope_table_kernel()
{
    int idx = blockIdx.x * 256 + threadIdx.x;    // 65536
    int j = idx & 31, s = idx >> 5;
    float inv = expf(-(float)j * (9.210340371976184f / 32.0f));
    float sn, cs;
    sincosf((float)s * inv, &sn, &cs);
    g_rope[idx] = make_float2(cs, sn);
}

// ---------------------------------------------------------------------------
// x -> half; skips rows >= ceil128(seq_len) (never read by QKV GEMM CTAs).
// ---------------------------------------------------------------------------
__global__ __launch_bounds__(256) void cvt_x_kernel(
    const float* __restrict__ x, const int* __restrict__ seq_lens)
{
    int idx = blockIdx.x * blockDim.x + threadIdx.x;   // over float4s
    int row = idx >> 8;                                 // 256 float4 per row
    int s = row & (SS - 1);
    if (s >= ((__ldg(&seq_lens[row >> 11]) + 127) & ~127)) return;
    float4 v = ((const float4*)x)[idx];
    uint2 u;
    u.x = h2u(__floats2half2_rn(v.x, v.y));
    u.y = h2u(__floats2half2_rn(v.z, v.w));
    ((uint2*)g_xh)[idx] = u;
}

// ---------------------------------------------------------------------------
// Weight transpose -> half. For Wq/Wk (z<2) the output column (head-dim) is
// permuted within each 64-wide head: old j<32 -> 2j, old j>=32 -> 2(j-32)+1.
// Q.K dot products are invariant (both permuted identically); this makes
// RoPE pairs register-adjacent in the GEMM epilogue.
// ---------------------------------------------------------------------------
__global__ __launch_bounds__(256) void transpose_kernel(
    const float* __restrict__ W0, const float* __restrict__ W1,
    const float* __restrict__ W2, const float* __restrict__ W3)
{
    __shared__ float tile[32][33];
    const int z = blockIdx.z;
    const float* W = (z == 0) ? W0 : (z == 1) ? W1 : (z == 2) ? W2 : W3;
    __half* T = g_Wth + (size_t)z * HID * HID;
    const int k0 = blockIdx.x * 32, n0 = blockIdx.y * 32;
    const int tx = threadIdx.x & 31, ty = threadIdx.x >> 5;
#pragma unroll
    for (int r = 0; r < 4; r++)
        tile[ty + r * 8][tx] = W[(size_t)(k0 + ty + r * 8) * HID + n0 + tx];
    __syncthreads();
#pragma unroll
    for (int r = 0; r < 4; r++) {
        int n = n0 + ty + r * 8;
        int dst = n;
        if (z < 2) {
            int jj = n & 63;
            dst = (n & ~63) | ((jj < 32) ? (jj << 1) : (((jj - 32) << 1) | 1));
        }
        T[(size_t)dst * HID + k0 + tx] = __float2half(tile[tx][ty + r * 8]);
    }
}

// ---------------------------------------------------------------------------
// fp16 GEMM, ldmatrix + 3-stage cp.async ring. Block 128x128, BK=32,
// 8 warps 2(M)x4(N), warp tile 64x32, 2 CTA/SM.
// MODE 0 (QKV): skip blocks >= ceil64(seq_len); fused RoPE rotation (+QSCALE
//   for Q) in the epilogue for Q/K column blocks (bn < 2048).
// MODE 1 (Wo): blocks >= seq_len write zeros.
// ---------------------------------------------------------------------------
#define GP 40

template <typename OUT, int MODE>
__global__ __launch_bounds__(256, 2) void rgemm_kernel(
    const __half* __restrict__ A, const __half* __restrict__ Bt,
    OUT* __restrict__ C, int ldc, const int* __restrict__ seq_lens)
{
    __shared__ __half As[3][128][GP];
    __shared__ __half Bs[3][128][GP];

    const int t    = threadIdx.x;
    const int bm   = blockIdx.y * 128;
    const int bn   = blockIdx.x * 128;

    const int slb = __ldg(&seq_lens[bm >> 11]);
    const int rloc = bm & (SS - 1);
    if (MODE == 0) {
        if (rloc >= ((slb + 63) & ~63)) return;
    } else {
        if (rloc >= slb) {
            for (int lin = t; lin < 128 * 32; lin += 256) {
                int r = lin >> 5, c4 = (lin & 31) * 4;
                *(float4*)((float*)C + (size_t)(bm + r) * ldc + bn + c4) =
                    make_float4(0.f, 0.f, 0.f, 0.f);
            }
            return;
        }
    }

    const int wid  = t >> 5, lane = t & 31;
    const int gid  = lane >> 2, q4 = lane & 3;
    const int wm   = wid & 1;
    const int wn   = wid >> 1;
    const int lrow = t >> 1;
    const int lch  = (t & 1) * 16;

    const __half* Ap = A  + (size_t)(bm + lrow) * HID + lch;
    const __half* Bp = Bt + (size_t)(bn + lrow) * HID + lch;

    uint32_t sa[3], sb[3];
#pragma unroll
    for (int s = 0; s < 3; s++) {
        sa[s] = sptr(&As[s][lrow][lch]);
        sb[s] = sptr(&Bs[s][lrow][lch]);
    }

#define LD_STAGE(s, ko)                                   \
    do {                                                  \
        CP16(sa[s],      Ap + (ko));                      \
        CP16(sa[s] + 16, Ap + (ko) + 8);                  \
        CP16(sb[s],      Bp + (ko));                      \
        CP16(sb[s] + 16, Bp + (ko) + 8);                  \
    } while (0)

    float acc[4][4][4];
#pragma unroll
    for (int mi = 0; mi < 4; mi++)
#pragma unroll
        for (int ni = 0; ni < 4; ni++)
#pragma unroll
            for (int e = 0; e < 4; e++) acc[mi][ni][e] = 0.f;

    LD_STAGE(0, 0);
    CP_COMMIT();
    LD_STAGE(1, 32);
    CP_COMMIT();
    CP_WAIT(1);
    __syncthreads();

    const int arow = (lane & 15), acol8 = (lane >> 4) * 8;
    const int brow = ((lane >> 4) & 1) * 8 + (lane & 7), bcol8 = ((lane >> 3) & 1) * 8;

    const int NT = HID / 32;
    int cur = 0;
    for (int k = 0; k < NT; k++) {
        if (k + 2 < NT) {
            int ps = cur + 2; if (ps >= 3) ps -= 3;
            LD_STAGE(ps, (k + 2) * 32);
        }
        CP_COMMIT();

#pragma unroll
        for (int kf = 0; kf < 2; kf++) {
            uint32_t af[4][4], bf[4][2];
#pragma unroll
            for (int mi = 0; mi < 4; mi++) {
                uint32_t ad = sptr(&As[cur][wm * 64 + mi * 16 + arow][kf * 16 + acol8]);
                LDSM_X4(af[mi][0], af[mi][1], af[mi][2], af[mi][3], ad);
            }
#pragma unroll
            for (int np = 0; np < 2; np++) {
                uint32_t bd = sptr(&Bs[cur][wn * 32 + np * 16 + brow][kf * 16 + bcol8]);
                LDSM_X4(bf[2 * np][0], bf[2 * np][1],
                        bf[2 * np + 1][0], bf[2 * np + 1][1], bd);
            }
#pragma unroll
            for (int mi = 0; mi < 4; mi++)
#pragma unroll
                for (int ni = 0; ni < 4; ni++)
                    mma_f16(acc[mi][ni], af[mi], bf[ni]);
        }

        CP_WAIT(1);
        __syncthreads();
        cur++; if (cur >= 3) cur = 0;
    }
#undef LD_STAGE

    // Epilogue. MODE 0: fused RoPE on Q/K column blocks.
    const bool isQK = (MODE == 0) && (bn < 2 * HID);
    const float qsc = (MODE == 0 && bn < HID) ? QSCALE : 1.0f;

#pragma unroll
    for (int mi = 0; mi < 4; mi++) {
        const int r0 = bm + wm * 64 + mi * 16 + gid;
        const int s0 = r0 & (SS - 1), s1 = (r0 + 8) & (SS - 1);
#pragma unroll
        for (int ni = 0; ni < 4; ni++) {
            const int col = bn + wn * 32 + ni * 8 + 2 * q4;
            float a0 = acc[mi][ni][0], a1 = acc[mi][ni][1];
            float a2 = acc[mi][ni][2], a3 = acc[mi][ni][3];
            if (isQK) {
                const int j = (col & 63) >> 1;
                float2 t0 = g_rope[s0 * 32 + j];
                float2 t1 = g_rope[s1 * 32 + j];
                float y0 = (a0 * t0.x - a1 * t0.y) * qsc;
                float y1 = (a1 * t0.x + a0 * t0.y) * qsc;
                float y2 = (a2 * t1.x - a3 * t1.y) * qsc;
                float y3 = (a3 * t1.x + a2 * t1.y) * qsc;
                a0 = y0; a1 = y1; a2 = y2; a3 = y3;
            }
            if (sizeof(OUT) == 2) {
                *(uint32_t*)((__half*)C + (size_t)r0 * ldc + col) =
                    h2u(__floats2half2_rn(a0, a1));
                *(uint32_t*)((__half*)C + (size_t)(r0 + 8) * ldc + col) =
                    h2u(__floats2half2_rn(a2, a3));
            } else {
                *(float2*)((float*)C + (size_t)r0 * ldc + col) = make_float2(a0, a1);
                *(float2*)((float*)C + (size_t)(r0 + 8) * ldc + col) = make_float2(a2, a3);
            }
        }
    }
}

// ---------------------------------------------------------------------------
// Flash attention (frozen from R14): fp16 mma + ldmatrix + 3-stage cp.async
// KV ring, single barrier per tile, register-resident P, log2-domain softmax.
// ---------------------------------------------------------------------------
#define FP 72

__global__ __launch_bounds__(256, 2) void flashmma_kernel(
    const __half* __restrict__ QKV, __half* __restrict__ AO,
    const int* __restrict__ seq_lens)
{
    extern __shared__ __half smh[];
    __half* Ps = smh;                      // [128][FP] (Q staging)
    __half* Ks = Ps + 128 * FP;            // [3][64][FP]
    __half* Vs = Ks + 3 * 64 * FP;         // [3][64][FP]

    const int bx = (SS / 128 - 1) - blockIdx.x;   // heavy-first ordering
    const int h = blockIdx.y, b = blockIdx.z;
    const int sl = __ldg(&seq_lens[b]);
    const int q0 = bx * 128;
    const int t  = threadIdx.x;
    const int wid = t >> 5, lane = t & 31;
    const int gid = lane >> 2, q4 = lane & 3;
    const int wr  = wid * 16;

    const size_t qkv_base = (size_t)b * SS * QKVW + (size_t)h * HD;
    const size_t ao_base  = (size_t)b * SS * HID  + (size_t)h * HD;

    if (q0 >= sl) {
        for (int lin = t; lin < 128 * 8; lin += 256) {
            int r = lin >> 3, c8 = (lin & 7) * 8;
            *(uint4*)(AO + ao_base + (size_t)(q0 + r) * HID + c8) =
                make_uint4(0, 0, 0, 0);
        }
        return;
    }

    const int lr0 = t >> 2, lc0 = (t & 3) * 16;
#define LD_KV(stage, k0)                                                       \
    do {                                                                       \
        size_t off = qkv_base + (size_t)((k0) + lr0) * QKVW + lc0;             \
        uint32_t dk = sptr(&Ks[(stage) * 64 * FP + lr0 * FP + lc0]);           \
        uint32_t dv = sptr(&Vs[(stage) * 64 * FP + lr0 * FP + lc0]);           \
        CP16(dk,      QKV + off + HID);                                        \
        CP16(dk + 16, QKV + off + HID + 8);                                    \
        CP16(dv,      QKV + off + 2 * HID);                                    \
        CP16(dv + 16, QKV + off + 2 * HID + 8);                                \
    } while (0)

    const int n_kt = min(2 * bx + 2, (sl + 63) >> 6);

    LD_KV(0, 0);
    if (n_kt > 1) LD_KV(1, 64);
    for (int lin = t; lin < 128 * 8; lin += 256) {
        int r = lin >> 3, c8 = (lin & 7) * 8;
        CP16(sptr(&Ps[r * FP + c8]),
             QKV + qkv_base + (size_t)(q0 + r) * QKVW + c8);
    }
    CP_COMMIT();
    CP_WAIT(0);
    __syncthreads();

    const int arow = lane & 15, acol8 = (lane >> 4) * 8;
    uint32_t qa[4][4];
#pragma unroll
    for (int kf = 0; kf < 4; kf++) {
        uint32_t ad = sptr(&Ps[(wr + arow) * FP + kf * 16 + acol8]);
        LDSM_X4(qa[kf][0], qa[kf][1], qa[kf][2], qa[kf][3], ad);
    }

    float ofr[8][4];
#pragma unroll
    for (int nf = 0; nf < 8; nf++)
#pragma unroll
        for (int e = 0; e < 4; e++) ofr[nf][e] = 0.f;
    float m0 = -1e30f, m1 = -1e30f, l0 = 0.f, l1 = 0.f;

    const int r0g = q0 + wr + gid;
    const int r1g = r0g + 8;

    const int krow = lane & 7, kcol8 = (lane >> 3) * 8;
    const int vrow = lane & 15, vcol8 = ((lane >> 4) & 1) * 8;

    int cur = 0;
    for (int kt = 0; kt < n_kt; kt++) {
        const int k0 = kt * 64;

        __syncthreads();
        if (kt + 2 < n_kt) {
            int ps = cur + 2; if (ps >= 3) ps -= 3;
            LD_KV(ps, k0 + 128);
        }
        CP_COMMIT();
        CP_WAIT(1);

        const __half* Kc = Ks + cur * 64 * FP;
        const __half* Vc = Vs + cur * 64 * FP;

        float sfr[8][4];
#pragma unroll
        for (int nf = 0; nf < 8; nf++) {
#pragma unroll
            for (int e = 0; e < 4; e++) sfr[nf][e] = 0.f;
            uint32_t kb[4][2];
            uint32_t d0 = sptr(&Kc[(nf * 8 + krow) * FP + kcol8]);
            LDSM_X4(kb[0][0], kb[0][1], kb[1][0], kb[1][1], d0);
            uint32_t d1 = sptr(&Kc[(nf * 8 + krow) * FP + 32 + kcol8]);
            LDSM_X4(kb[2][0], kb[2][1], kb[3][0], kb[3][1], d1);
#pragma unroll
            for (int kf = 0; kf < 4; kf++)
                mma_f16(sfr[nf], qa[kf], kb[kf]);
        }

        if (k0 + 63 > q0 + wr) {
#pragma unroll
            for (int nf = 0; nf < 8; nf++) {
                int c0 = k0 + nf * 8 + 2 * q4, c1 = c0 + 1;
                if (c0 > r0g) sfr[nf][0] = -1e30f;
                if (c1 > r0g) sfr[nf][1] = -1e30f;
                if (c0 > r1g) sfr[nf][2] = -1e30f;
                if (c1 > r1g) sfr[nf][3] = -1e30f;
            }
        }

        float tm0 = -1e30f, tm1 = -1e30f;
#pragma unroll
        for (int nf = 0; nf < 8; nf++) {
            tm0 = fmaxf(tm0, fmaxf(sfr[nf][0], sfr[nf][1]));
            tm1 = fmaxf(tm1, fmaxf(sfr[nf][2], sfr[nf][3]));
        }
        tm0 = fmaxf(tm0, __shfl_xor_sync(0xffffffffu, tm0, 1));
        tm0 = fmaxf(tm0, __shfl_xor_sync(0xffffffffu, tm0, 2));
        tm1 = fmaxf(tm1, __shfl_xor_sync(0xffffffffu, tm1, 1));
        tm1 = fmaxf(tm1, __shfl_xor_sync(0xffffffffu, tm1, 2));

        float mn0 = fmaxf(m0, tm0), mn1 = fmaxf(m1, tm1);
        float corr0 = ex2f(m0 - mn0), corr1 = ex2f(m1 - mn1);
        m0 = mn0; m1 = mn1;

        float s0 = 0.f, s1 = 0.f;
#pragma unroll
        for (int nf = 0; nf < 8; nf++) {
            float p0 = ex2f(sfr[nf][0] - mn0);
            float p1 = ex2f(sfr[nf][1] - mn0);
            float p2 = ex2f(sfr[nf][2] - mn1);
            float p3 = ex2f(sfr[nf][3] - mn1);
            s0 += p0 + p1; s1 += p2 + p3;
            sfr[nf][0] = p0; sfr[nf][1] = p1;
            sfr[nf][2] = p2; sfr[nf][3] = p3;
        }
        s0 += __shfl_xor_sync(0xffffffffu, s0, 1);
        s0 += __shfl_xor_sync(0xffffffffu, s0, 2);
        s1 += __shfl_xor_sync(0xffffffffu, s1, 1);
        s1 += __shfl_xor_sync(0xffffffffu, s1, 2);
        l0 = l0 * corr0 + s0;
        l1 = l1 * corr1 + s1;

#pragma unroll
        for (int nf = 0; nf < 8; nf++) {
            ofr[nf][0] *= corr0; ofr[nf][1] *= corr0;
            ofr[nf][2] *= corr1; ofr[nf][3] *= corr1;
        }

        uint32_t pa[4][4];
#pragma unroll
        for (int kf = 0; kf < 4; kf++) {
            pa[kf][0] = h2u(__floats2half2_rn(sfr[2 * kf][0],     sfr[2 * kf][1]));
            pa[kf][1] = h2u(__floats2half2_rn(sfr[2 * kf][2],     sfr[2 * kf][3]));
            pa[kf][2] = h2u(__floats2half2_rn(sfr[2 * kf + 1][0], sfr[2 * kf + 1][1]));
            pa[kf][3] = h2u(__floats2half2_rn(sfr[2 * kf + 1][2], sfr[2 * kf + 1][3]));
        }

#pragma unroll
        for (int np = 0; np < 4; np++) {
#pragma unroll
            for (int kf = 0; kf < 4; kf++) {
                uint32_t v0, v1, v2, v3;
                uint32_t vd = sptr(&Vc[(kf * 16 + vrow) * FP + np * 16 + vcol8]);
                LDSM_X4T(v0, v1, v2, v3, vd);
                uint32_t blo[2] = {v0, v1}, bhi[2] = {v2, v3};
                mma_f16(ofr[2 * np], pa[kf], blo);
                mma_f16(ofr[2 * np + 1], pa[kf], bhi);
            }
        }

        cur++; if (cur >= 3) cur = 0;
    }
#undef LD_KV

    const float inv0 = (r0g < sl) ? (1.f / l0) : 0.f;
    const float inv1 = (r1g < sl) ? (1.f / l1) : 0.f;
#pragma unroll
    for (int nf = 0; nf < 8; nf++) {
        *(uint32_t*)(AO + ao_base + (size_t)r0g * HID + nf * 8 + 2 * q4) =
            h2u(__floats2half2_rn(ofr[nf][0] * inv0, ofr[nf][1] * inv0));
        *(uint32_t*)(AO + ao_base + (size_t)r1g * HID + nf * 8 + 2 * q4) =
            h2u(__floats2half2_rn(ofr[nf][2] * inv1, ofr[nf][3] * inv1));
    }
}

// ---------------------------------------------------------------------------
extern "C" void kernel_launch(void* const* d_in, const int* in_sizes, int n_in,
                              void* d_out, int out_size)
{
    (void)in_sizes; (void)n_in; (void)out_size;
    const float* x  = (const float*)d_in[0];
    const float* Wq = (const float*)d_in[1];
    const float* Wk = (const float*)d_in[2];
    const float* Wv = (const float*)d_in[3];
    const float* Wo = (const float*)d_in[4];
    const int*   sl = (const int*)d_in[5];
    float* out = (float*)d_out;

    __half *xh, *QKVh, *AOh, *Wth;
    cudaGetSymbolAddress((void**)&xh,   g_xh);
    cudaGetSymbolAddress((void**)&QKVh, g_QKVh);
    cudaGetSymbolAddress((void**)&AOh,  g_AOh);
    cudaGetSymbolAddress((void**)&Wth,  g_Wth);

    const int FLASH_SMEM = (128 + 6 * 64) * FP * (int)sizeof(__half); // 73728
    cudaFuncSetAttribute(flashmma_kernel,
                         cudaFuncAttributeMaxDynamicSharedMemorySize, FLASH_SMEM);

    rope_table_kernel<<<(SS * 32) / 256, 256>>>();
    cvt_x_kernel<<<(ROWS * HID / 4) / 256, 256>>>(x, sl);
    transpose_kernel<<<dim3(32, 32, 4), 256>>>(Wq, Wk, Wv, Wo);

    // Fused QKV GEMM with in-epilogue RoPE (+QSCALE on Q)
    rgemm_kernel<__half, 0><<<dim3(QKVW / 128, ROWS / 128), 256>>>(
        xh, Wth, QKVh, QKVW, sl);

    dim3 flash_grid(SS / 128, NH, BB);
    flashmma_kernel<<<flash_grid, 256, FLASH_SMEM>>>(QKVh, AOh, sl);

    rgemm_kernel<float, 1><<<dim3(HID / 128, ROWS / 128), 256>>>(
        AOh, Wth + 3 * (size_t)HID * HID, out, HID, sl);
}

// round 16
// speedup vs baseline: 1.3842x; 1.0141x over previous
#include <cuda_runtime.h>
#include <cuda_fp16.h>
#include <cstdint>
#include <math.h>

#define BB   4
#define SS   2048
#define HID  1024
#define NH   16
#define HD   64
#define ROWS (BB*SS)
#define QKVW (3*HID)
#define QSCALE 0.18033688011112042f  // (1/sqrt(64)) * log2(e)

// Scratch (alloc-free rule: __device__ globals)
__device__ __half g_xh[ROWS * HID];
__device__ __half g_QKVh[ROWS * QKVW];
__device__ __half g_AOh[ROWS * HID];
__device__ __half g_Wth[4 * HID * HID];
__device__ float2 g_rope[SS * 32];        // [s][j] = (cos, sin)

__device__ __forceinline__ void mma_f16(float* d, const uint32_t* a,
                                        const uint32_t* b) {
    asm volatile(
        "mma.sync.aligned.m16n8k16.row.col.f32.f16.f16.f32 "
        "{%0,%1,%2,%3}, {%4,%5,%6,%7}, {%8,%9}, {%0,%1,%2,%3};\n"
        : "+f"(d[0]), "+f"(d[1]), "+f"(d[2]), "+f"(d[3])
        : "r"(a[0]), "r"(a[1]), "r"(a[2]), "r"(a[3]), "r"(b[0]), "r"(b[1]));
}
__device__ __forceinline__ uint32_t h2u(__half2 h) { return *(uint32_t*)&h; }
__device__ __forceinline__ float ex2f(float x) {
    float r;
    asm("ex2.approx.f32 %0, %1;" : "=f"(r) : "f"(x));
    return r;
}
__device__ __forceinline__ uint32_t sptr(const void* p) {
    uint32_t a;
    asm("{ .reg .u64 t; cvta.to.shared.u64 t, %1; cvt.u32.u64 %0, t; }"
        : "=r"(a) : "l"(p));
    return a;
}
#define LDSM_X4(r0, r1, r2, r3, addr)                                          \
    asm volatile("ldmatrix.sync.aligned.m8n8.x4.shared.b16 {%0,%1,%2,%3}, [%4];" \
                 : "=r"(r0), "=r"(r1), "=r"(r2), "=r"(r3) : "r"(addr))
#define LDSM_X4T(r0, r1, r2, r3, addr)                                         \
    asm volatile("ldmatrix.sync.aligned.m8n8.x4.trans.shared.b16 {%0,%1,%2,%3}, [%4];" \
                 : "=r"(r0), "=r"(r1), "=r"(r2), "=r"(r3) : "r"(addr))
#define CP16(dst, src)                                                         \
    asm volatile("cp.async.cg.shared.global [%0], [%1], 16;"                   \
                 :: "r"(dst), "l"(src))
#define CP_COMMIT() asm volatile("cp.async.commit_group;" ::: "memory")
#define CP_WAIT(n)  asm volatile("cp.async.wait_group %0;" :: "n"(n) : "memory")

// ---------------------------------------------------------------------------
// Fused prep: one launch covering
//   [0, 8192)        x -> half (skip rows >= ceil128(seq_len))
//   [8192, 12288)    weight transpose -> half (RoPE column permutation on Wq/Wk)
//   [12288, 12544)   RoPE cos/sin table
// ---------------------------------------------------------------------------
#define CVT_BLOCKS 8192
#define TR_BLOCKS  4096
#define PREP_BLOCKS (CVT_BLOCKS + TR_BLOCKS + 256)

__global__ __launch_bounds__(256) void prep_kernel(
    const float* __restrict__ x,
    const float* __restrict__ W0, const float* __restrict__ W1,
    const float* __restrict__ W2, const float* __restrict__ W3,
    const int* __restrict__ seq_lens)
{
    __shared__ float tile[32][33];
    const int bid = blockIdx.x;

    if (bid < CVT_BLOCKS) {
        // x -> half
        int idx = bid * 256 + threadIdx.x;              // over float4s
        int row = idx >> 8;                             // 256 float4 per row
        int s = row & (SS - 1);
        if (s >= ((__ldg(&seq_lens[row >> 11]) + 127) & ~127)) return;
        float4 v = ((const float4*)x)[idx];
        uint2 u;
        u.x = h2u(__floats2half2_rn(v.x, v.y));
        u.y = h2u(__floats2half2_rn(v.z, v.w));
        ((uint2*)g_xh)[idx] = u;
    } else if (bid < CVT_BLOCKS + TR_BLOCKS) {
        // Weight transpose (with RoPE pair-permutation for Wq/Wk)
        int lb = bid - CVT_BLOCKS;
        const int z = lb >> 10;                         // 0..3
        int wb = lb & 1023;                             // 32x32 tile grid
        const int k0 = (wb & 31) * 32, n0 = (wb >> 5) * 32;
        const float* W = (z == 0) ? W0 : (z == 1) ? W1 : (z == 2) ? W2 : W3;
        __half* T = g_Wth + (size_t)z * HID * HID;
        const int tx = threadIdx.x & 31, ty = threadIdx.x >> 5;
#pragma unroll
        for (int r = 0; r < 4; r++)
            tile[ty + r * 8][tx] = W[(size_t)(k0 + ty + r * 8) * HID + n0 + tx];
        __syncthreads();
#pragma unroll
        for (int r = 0; r < 4; r++) {
            int n = n0 + ty + r * 8;
            int dst = n;
            if (z < 2) {
                int jj = n & 63;
                dst = (n & ~63) | ((jj < 32) ? (jj << 1) : (((jj - 32) << 1) | 1));
            }
            T[(size_t)dst * HID + k0 + tx] = __float2half(tile[tx][ty + r * 8]);
        }
    } else {
        // RoPE table
        int idx = (bid - CVT_BLOCKS - TR_BLOCKS) * 256 + threadIdx.x;  // 65536
        int j = idx & 31, s = idx >> 5;
        float inv = expf(-(float)j * (9.210340371976184f / 32.0f));
        float sn, cs;
        sincosf((float)s * inv, &sn, &cs);
        g_rope[idx] = make_float2(cs, sn);
    }
}

// ---------------------------------------------------------------------------
// fp16 GEMM, ldmatrix + 3-stage cp.async ring. Block 128x128, BK=32,
// 8 warps 2(M)x4(N), warp tile 64x32, 2 CTA/SM.
// MODE 0 (QKV): skip blocks >= ceil64(seq_len); fused RoPE in epilogue.
// MODE 1 (Wo): blocks >= seq_len write zeros.
// ---------------------------------------------------------------------------
#define GP 40

template <typename OUT, int MODE>
__global__ __launch_bounds__(256, 2) void rgemm_kernel(
    const __half* __restrict__ A, const __half* __restrict__ Bt,
    OUT* __restrict__ C, int ldc, const int* __restrict__ seq_lens)
{
    __shared__ __half As[3][128][GP];
    __shared__ __half Bs[3][128][GP];

    const int t    = threadIdx.x;
    const int bm   = blockIdx.y * 128;
    const int bn   = blockIdx.x * 128;

    const int slb = __ldg(&seq_lens[bm >> 11]);
    const int rloc = bm & (SS - 1);
    if (MODE == 0) {
        if (rloc >= ((slb + 63) & ~63)) return;
    } else {
        if (rloc >= slb) {
            for (int lin = t; lin < 128 * 32; lin += 256) {
                int r = lin >> 5, c4 = (lin & 31) * 4;
                *(float4*)((float*)C + (size_t)(bm + r) * ldc + bn + c4) =
                    make_float4(0.f, 0.f, 0.f, 0.f);
            }
            return;
        }
    }

    const int wid  = t >> 5, lane = t & 31;
    const int gid  = lane >> 2, q4 = lane & 3;
    const int wm   = wid & 1;
    const int wn   = wid >> 1;
    const int lrow = t >> 1;
    const int lch  = (t & 1) * 16;

    const __half* Ap = A  + (size_t)(bm + lrow) * HID + lch;
    const __half* Bp = Bt + (size_t)(bn + lrow) * HID + lch;

    uint32_t sa[3], sb[3];
#pragma unroll
    for (int s = 0; s < 3; s++) {
        sa[s] = sptr(&As[s][lrow][lch]);
        sb[s] = sptr(&Bs[s][lrow][lch]);
    }

#define LD_STAGE(s, ko)                                   \
    do {                                                  \
        CP16(sa[s],      Ap + (ko));                      \
        CP16(sa[s] + 16, Ap + (ko) + 8);                  \
        CP16(sb[s],      Bp + (ko));                      \
        CP16(sb[s] + 16, Bp + (ko) + 8);                  \
    } while (0)

    float acc[4][4][4];
#pragma unroll
    for (int mi = 0; mi < 4; mi++)
#pragma unroll
        for (int ni = 0; ni < 4; ni++)
#pragma unroll
            for (int e = 0; e < 4; e++) acc[mi][ni][e] = 0.f;

    LD_STAGE(0, 0);
    CP_COMMIT();
    LD_STAGE(1, 32);
    CP_COMMIT();
    CP_WAIT(1);
    __syncthreads();

    const int arow = (lane & 15), acol8 = (lane >> 4) * 8;
    const int brow = ((lane >> 4) & 1) * 8 + (lane & 7), bcol8 = ((lane >> 3) & 1) * 8;

    const int NT = HID / 32;
    int cur = 0;
    for (int k = 0; k < NT; k++) {
        if (k + 2 < NT) {
            int ps = cur + 2; if (ps >= 3) ps -= 3;
            LD_STAGE(ps, (k + 2) * 32);
        }
        CP_COMMIT();

#pragma unroll
        for (int kf = 0; kf < 2; kf++) {
            uint32_t af[4][4], bf[4][2];
#pragma unroll
            for (int mi = 0; mi < 4; mi++) {
                uint32_t ad = sptr(&As[cur][wm * 64 + mi * 16 + arow][kf * 16 + acol8]);
                LDSM_X4(af[mi][0], af[mi][1], af[mi][2], af[mi][3], ad);
            }
#pragma unroll
            for (int np = 0; np < 2; np++) {
                uint32_t bd = sptr(&Bs[cur][wn * 32 + np * 16 + brow][kf * 16 + bcol8]);
                LDSM_X4(bf[2 * np][0], bf[2 * np][1],
                        bf[2 * np + 1][0], bf[2 * np + 1][1], bd);
            }
#pragma unroll
            for (int mi = 0; mi < 4; mi++)
#pragma unroll
                for (int ni = 0; ni < 4; ni++)
                    mma_f16(acc[mi][ni], af[mi], bf[ni]);
        }

        CP_WAIT(1);
        __syncthreads();
        cur++; if (cur >= 3) cur = 0;
    }
#undef LD_STAGE

    // Epilogue. MODE 0: fused RoPE on Q/K column blocks.
    const bool isQK = (MODE == 0) && (bn < 2 * HID);
    const float qsc = (MODE == 0 && bn < HID) ? QSCALE : 1.0f;

#pragma unroll
    for (int mi = 0; mi < 4; mi++) {
        const int r0 = bm + wm * 64 + mi * 16 + gid;
        const int s0 = r0 & (SS - 1), s1 = (r0 + 8) & (SS - 1);
#pragma unroll
        for (int ni = 0; ni < 4; ni++) {
            const int col = bn + wn * 32 + ni * 8 + 2 * q4;
            float a0 = acc[mi][ni][0], a1 = acc[mi][ni][1];
            float a2 = acc[mi][ni][2], a3 = acc[mi][ni][3];
            if (isQK) {
                const int j = (col & 63) >> 1;
                float2 t0 = g_rope[s0 * 32 + j];
                float2 t1 = g_rope[s1 * 32 + j];
                float y0 = (a0 * t0.x - a1 * t0.y) * qsc;
                float y1 = (a1 * t0.x + a0 * t0.y) * qsc;
                float y2 = (a2 * t1.x - a3 * t1.y) * qsc;
                float y3 = (a3 * t1.x + a2 * t1.y) * qsc;
                a0 = y0; a1 = y1; a2 = y2; a3 = y3;
            }
            if (sizeof(OUT) == 2) {
                *(uint32_t*)((__half*)C + (size_t)r0 * ldc + col) =
                    h2u(__floats2half2_rn(a0, a1));
                *(uint32_t*)((__half*)C + (size_t)(r0 + 8) * ldc + col) =
                    h2u(__floats2half2_rn(a2, a3));
            } else {
                *(float2*)((float*)C + (size_t)r0 * ldc + col) = make_float2(a0, a1);
                *(float2*)((float*)C + (size_t)(r0 + 8) * ldc + col) = make_float2(a2, a3);
            }
        }
    }
}

// ---------------------------------------------------------------------------
// Flash attention: fp16 mma + ldmatrix + 3-stage cp.async KV ring, single
// barrier per tile, register-resident P, log2-domain softmax.
// Fully-invalid q-tiles (q0 >= sl) return WITHOUT writing: those AOh rows are
// provably never read (Wo skips row-blocks >= sl; boundary rows are written
// by the partial flash tile with q0 < sl).
// ---------------------------------------------------------------------------
#define FP 72

__global__ __launch_bounds__(256, 2) void flashmma_kernel(
    const __half* __restrict__ QKV, __half* __restrict__ AO,
    const int* __restrict__ seq_lens)
{
    extern __shared__ __half smh[];
    __half* Ps = smh;                      // [128][FP] (Q staging)
    __half* Ks = Ps + 128 * FP;            // [3][64][FP]
    __half* Vs = Ks + 3 * 64 * FP;         // [3][64][FP]

    const int bx = (SS / 128 - 1) - blockIdx.x;   // heavy-first ordering
    const int h = blockIdx.y, b = blockIdx.z;
    const int sl = __ldg(&seq_lens[b]);
    const int q0 = bx * 128;
    if (q0 >= sl) return;                  // rows never read downstream

    const int t  = threadIdx.x;
    const int wid = t >> 5, lane = t & 31;
    const int gid = lane >> 2, q4 = lane & 3;
    const int wr  = wid * 16;

    const size_t qkv_base = (size_t)b * SS * QKVW + (size_t)h * HD;
    const size_t ao_base  = (size_t)b * SS * HID  + (size_t)h * HD;

    const int lr0 = t >> 2, lc0 = (t & 3) * 16;
#define LD_KV(stage, k0)                                                       \
    do {                                                                       \
        size_t off = qkv_base + (size_t)((k0) + lr0) * QKVW + lc0;             \
        uint32_t dk = sptr(&Ks[(stage) * 64 * FP + lr0 * FP + lc0]);           \
        uint32_t dv = sptr(&Vs[(stage) * 64 * FP + lr0 * FP + lc0]);           \
        CP16(dk,      QKV + off + HID);                                        \
        CP16(dk + 16, QKV + off + HID + 8);                                    \
        CP16(dv,      QKV + off + 2 * HID);                                    \
        CP16(dv + 16, QKV + off + 2 * HID + 8);                                \
    } while (0)

    const int n_kt = min(2 * bx + 2, (sl + 63) >> 6);

    LD_KV(0, 0);
    if (n_kt > 1) LD_KV(1, 64);
    for (int lin = t; lin < 128 * 8; lin += 256) {
        int r = lin >> 3, c8 = (lin & 7) * 8;
        CP16(sptr(&Ps[r * FP + c8]),
             QKV + qkv_base + (size_t)(q0 + r) * QKVW + c8);
    }
    CP_COMMIT();
    CP_WAIT(0);
    __syncthreads();

    const int arow = lane & 15, acol8 = (lane >> 4) * 8;
    uint32_t qa[4][4];
#pragma unroll
    for (int kf = 0; kf < 4; kf++) {
        uint32_t ad = sptr(&Ps[(wr + arow) * FP + kf * 16 + acol8]);
        LDSM_X4(qa[kf][0], qa[kf][1], qa[kf][2], qa[kf][3], ad);
    }

    float ofr[8][4];
#pragma unroll
    for (int nf = 0; nf < 8; nf++)
#pragma unroll
        for (int e = 0; e < 4; e++) ofr[nf][e] = 0.f;
    float m0 = -1e30f, m1 = -1e30f, l0 = 0.f, l1 = 0.f;

    const int r0g = q0 + wr + gid;
    const int r1g = r0g + 8;

    const int krow = lane & 7, kcol8 = (lane >> 3) * 8;
    const int vrow = lane & 15, vcol8 = ((lane >> 4) & 1) * 8;

    int cur = 0;
    for (int kt = 0; kt < n_kt; kt++) {
        const int k0 = kt * 64;

        __syncthreads();
        if (kt + 2 < n_kt) {
            int ps = cur + 2; if (ps >= 3) ps -= 3;
            LD_KV(ps, k0 + 128);
        }
        CP_COMMIT();
        CP_WAIT(1);

        const __half* Kc = Ks + cur * 64 * FP;
        const __half* Vc = Vs + cur * 64 * FP;

        float sfr[8][4];
#pragma unroll
        for (int nf = 0; nf < 8; nf++) {
#pragma unroll
            for (int e = 0; e < 4; e++) sfr[nf][e] = 0.f;
            uint32_t kb[4][2];
            uint32_t d0 = sptr(&Kc[(nf * 8 + krow) * FP + kcol8]);
            LDSM_X4(kb[0][0], kb[0][1], kb[1][0], kb[1][1], d0);
            uint32_t d1 = sptr(&Kc[(nf * 8 + krow) * FP + 32 + kcol8]);
            LDSM_X4(kb[2][0], kb[2][1], kb[3][0], kb[3][1], d1);
#pragma unroll
            for (int kf = 0; kf < 4; kf++)
                mma_f16(sfr[nf], qa[kf], kb[kf]);
        }

        if (k0 + 63 > q0 + wr) {
#pragma unroll
            for (int nf = 0; nf < 8; nf++) {
                int c0 = k0 + nf * 8 + 2 * q4, c1 = c0 + 1;
                if (c0 > r0g) sfr[nf][0] = -1e30f;
                if (c1 > r0g) sfr[nf][1] = -1e30f;
                if (c0 > r1g) sfr[nf][2] = -1e30f;
                if (c1 > r1g) sfr[nf][3] = -1e30f;
            }
        }

        float tm0 = -1e30f, tm1 = -1e30f;
#pragma unroll
        for (int nf = 0; nf < 8; nf++) {
            tm0 = fmaxf(tm0, fmaxf(sfr[nf][0], sfr[nf][1]));
            tm1 = fmaxf(tm1, fmaxf(sfr[nf][2], sfr[nf][3]));
        }
        tm0 = fmaxf(tm0, __shfl_xor_sync(0xffffffffu, tm0, 1));
        tm0 = fmaxf(tm0, __shfl_xor_sync(0xffffffffu, tm0, 2));
        tm1 = fmaxf(tm1, __shfl_xor_sync(0xffffffffu, tm1, 1));
        tm1 = fmaxf(tm1, __shfl_xor_sync(0xffffffffu, tm1, 2));

        float mn0 = fmaxf(m0, tm0), mn1 = fmaxf(m1, tm1);
        float corr0 = ex2f(m0 - mn0), corr1 = ex2f(m1 - mn1);
        m0 = mn0; m1 = mn1;

        float s0 = 0.f, s1 = 0.f;
#pragma unroll
        for (int nf = 0; nf < 8; nf++) {
            float p0 = ex2f(sfr[nf][0] - mn0);
            float p1 = ex2f(sfr[nf][1] - mn0);
            float p2 = ex2f(sfr[nf][2] - mn1);
            float p3 = ex2f(sfr[nf][3] - mn1);
            s0 += p0 + p1; s1 += p2 + p3;
            sfr[nf][0] = p0; sfr[nf][1] = p1;
            sfr[nf][2] = p2; sfr[nf][3] = p3;
        }
        s0 += __shfl_xor_sync(0xffffffffu, s0, 1);
        s0 += __shfl_xor_sync(0xffffffffu, s0, 2);
        s1 += __shfl_xor_sync(0xffffffffu, s1, 1);
        s1 += __shfl_xor_sync(0xffffffffu, s1, 2);
        l0 = l0 * corr0 + s0;
        l1 = l1 * corr1 + s1;

#pragma unroll
        for (int nf = 0; nf < 8; nf++) {
            ofr[nf][0] *= corr0; ofr[nf][1] *= corr0;
            ofr[nf][2] *= corr1; ofr[nf][3] *= corr1;
        }

        uint32_t pa[4][4];
#pragma unroll
        for (int kf = 0; kf < 4; kf++) {
            pa[kf][0] = h2u(__floats2half2_rn(sfr[2 * kf][0],     sfr[2 * kf][1]));
            pa[kf][1] = h2u(__floats2half2_rn(sfr[2 * kf][2],     sfr[2 * kf][3]));
            pa[kf][2] = h2u(__floats2half2_rn(sfr[2 * kf + 1][0], sfr[2 * kf + 1][1]));
            pa[kf][3] = h2u(__floats2half2_rn(sfr[2 * kf + 1][2], sfr[2 * kf + 1][3]));
        }

#pragma unroll
        for (int np = 0; np < 4; np++) {
#pragma unroll
            for (int kf = 0; kf < 4; kf++) {
                uint32_t v0, v1, v2, v3;
                uint32_t vd = sptr(&Vc[(kf * 16 + vrow) * FP + np * 16 + vcol8]);
                LDSM_X4T(v0, v1, v2, v3, vd);
                uint32_t blo[2] = {v0, v1}, bhi[2] = {v2, v3};
                mma_f16(ofr[2 * np], pa[kf], blo);
                mma_f16(ofr[2 * np + 1], pa[kf], bhi);
            }
        }

        cur++; if (cur >= 3) cur = 0;
    }
#undef LD_KV

    const float inv0 = (r0g < sl) ? (1.f / l0) : 0.f;
    const float inv1 = (r1g < sl) ? (1.f / l1) : 0.f;
#pragma unroll
    for (int nf = 0; nf < 8; nf++) {
        *(uint32_t*)(AO + ao_base + (size_t)r0g * HID + nf * 8 + 2 * q4) =
            h2u(__floats2half2_rn(ofr[nf][0] * inv0, ofr[nf][1] * inv0));
        *(uint32_t*)(AO + ao_base + (size_t)r1g * HID + nf * 8 + 2 * q4) =
            h2u(__floats2half2_rn(ofr[nf][2] * inv1, ofr[nf][3] * inv1));
    }
}

// ---------------------------------------------------------------------------
extern "C" void kernel_launch(void* const* d_in, const int* in_sizes, int n_in,
                              void* d_out, int out_size)
{
    (void)in_sizes; (void)n_in; (void)out_size;
    const float* x  = (const float*)d_in[0];
    const float* Wq = (const float*)d_in[1];
    const float* Wk = (const float*)d_in[2];
    const float* Wv = (const float*)d_in[3];
    const float* Wo = (const float*)d_in[4];
    const int*   sl = (const int*)d_in[5];
    float* out = (float*)d_out;

    __half *xh, *QKVh, *AOh, *Wth;
    cudaGetSymbolAddress((void**)&xh,   g_xh);
    cudaGetSymbolAddress((void**)&QKVh, g_QKVh);
    cudaGetSymbolAddress((void**)&AOh,  g_AOh);
    cudaGetSymbolAddress((void**)&Wth,  g_Wth);

    const int FLASH_SMEM = (128 + 6 * 64) * FP * (int)sizeof(__half); // 73728
    cudaFuncSetAttribute(flashmma_kernel,
                         cudaFuncAttributeMaxDynamicSharedMemorySize, FLASH_SMEM);

    prep_kernel<<<PREP_BLOCKS, 256>>>(x, Wq, Wk, Wv, Wo, sl);

    // Fused QKV GEMM with in-epilogue RoPE (+QSCALE on Q)
    rgemm_kernel<__half, 0><<<dim3(QKVW / 128, ROWS / 128), 256>>>(
        xh, Wth, QKVh, QKVW, sl);

    dim3 flash_grid(SS / 128, NH, BB);
    flashmma_kernel<<<flash_grid, 256, FLASH_SMEM>>>(QKVh, AOh, sl);

    rgemm_kernel<float, 1><<<dim3(HID / 128, ROWS / 128), 256>>>(
        AOh, Wth + 3 * (size_t)HID * HID, out, HID, sl);
}